// round 13
// baseline (speedup 1.0000x reference)
#include <cuda_runtime.h>
#include <math.h>
#include <stdint.h>

#define BB   4
#define CC   512
#define NBK  8
#define BSZ  64
#define WFM  33
#define KHM  64
#define NPTS (BB*KHM*WFM)     // 8448

// Z/D layout: [n][i][p]  (p = b*2112 + k*33 + wf) -> contiguous per image
__device__ float  g_Zr[NBK*BSZ*NPTS];
__device__ float  g_Zi[NBK*BSZ*NPTS];
__device__ float  g_Dr[NBK*BSZ*NPTS];
__device__ float  g_Di[NBK*BSZ*NPTS];
__device__ float  g_S[BB*CC*128*128];

__device__ uint32_t T1g[128*72];
__device__ uint32_t T2g[128*128];
__device__ uint32_t T3g[128*128];
__device__ uint32_t T4g[72*136];

__device__ __forceinline__ uint32_t f2tf32(float f) {
  uint32_t r; asm("cvt.rna.tf32.f32 %0, %1;" : "=r"(r) : "f"(f)); return r;
}
__device__ __forceinline__ void mma1688(float* d, const uint32_t* a, const uint32_t* b2) {
  asm volatile(
    "mma.sync.aligned.m16n8k8.row.col.f32.tf32.tf32.f32 "
    "{%0,%1,%2,%3}, {%4,%5,%6,%7}, {%8,%9}, {%0,%1,%2,%3};"
    : "+f"(d[0]), "+f"(d[1]), "+f"(d[2]), "+f"(d[3])
    : "r"(a[0]), "r"(a[1]), "r"(a[2]), "r"(a[3]), "r"(b2[0]), "r"(b2[1]));
}

// ---------------------------------------------------------------------------
__global__ __launch_bounds__(256) void k0_twiddle() {
  int tid = blockIdx.x*256 + threadIdx.x;
  for (int idx = tid; idx < 128*72; idx += 256*32) {
    int w = idx / 72, nf = idx % 72;
    float v = 0.f;
    if (nf < 33)      v =  cospif((float)((w*nf) & 127) * (1.0f/64.0f));
    else if (nf < 66) v = -sinpif((float)((w*(nf-33)) & 127) * (1.0f/64.0f));
    T1g[idx] = f2tf32(v);
  }
  for (int idx = tid; idx < 128*128; idx += 256*32) {
    int m = idx >> 7, h = idx & 127;
    float v = (m < 64) ? cospif((float)((h*m) & 127) * (1.0f/64.0f))
                       : sinpif((float)((h*(m-64)) & 127) * (1.0f/64.0f));
    T2g[idx] = f2tf32(v);
  }
  for (int idx = tid; idx < 128*128; idx += 256*32) {
    int h = idx >> 7, kk = idx & 127;
    float v = (kk < 64) ? cospif((float)((h*kk) & 127) * (1.0f/64.0f))
                        : sinpif((float)((h*(kk-64)) & 127) * (1.0f/64.0f));
    T3g[idx] = f2tf32(v);
  }
  for (int idx = tid; idx < 72*136; idx += 256*32) {
    int kk = idx / 136, w = idx % 136;
    float v = 0.f;
    if (w < 128) {
      if (kk == 0)       v = 1.0f/128.0f;
      else if (kk < 33)  v =  (1.0f/64.0f) * cospif((float)((w*kk) & 127) * (1.0f/64.0f));
      else if (kk == 33) v = 0.f;
      else if (kk < 66)  v = -(1.0f/64.0f) * sinpif((float)((w*(kk-33)) & 127) * (1.0f/64.0f));
    }
    T4g[idx] = f2tf32(v);
  }
}

// ---------------------------------------------------------------------------
// K12: fused forward. T1/T2 fragments direct from gmem; only x staged.
// smem: As[128][36] (x tf32) + B2[128][72] (F tf32 / O2 fp32) = 55296 B
// ---------------------------------------------------------------------------
__global__ __launch_bounds__(256) void k12_fwd(const float* __restrict__ x) {
  extern __shared__ uint32_t smw[];
  uint32_t* As = smw;            // [128][36]
  uint32_t* B2 = smw + 4608;     // [128][72]
  float* O2f = (float*)B2;

  int tid = threadIdx.x;
  int lane = tid & 31, wid = tid >> 5;
  int qr = lane >> 2, qc = lane & 3;
  int m0 = wid * 16;
  int bc = blockIdx.x;
  int b = bc >> 9, c = bc & 511;
  const float* xp = x + (size_t)bc * 16384;

  // ---- GEMM1: F = x @ T1 ----
  float acc[9][4];
  #pragma unroll
  for (int nt=0;nt<9;++nt) {
    #pragma unroll
    for (int r=0;r<4;++r) acc[nt][r]=0.f;
  }
  for (int kc = 0; kc < 128; kc += 32) {
    __syncthreads();
    #pragma unroll
    for (int it = 0; it < 16; ++it) {
      int s = it*256 + tid;
      int h = s >> 5, w = s & 31;
      As[h*36 + w] = f2tf32(xp[h*128 + kc + w]);
    }
    __syncthreads();
    #pragma unroll
    for (int ks = 0; ks < 4; ++ks) {
      int k8 = ks*8;
      uint32_t a[4];
      a[0] = As[(m0+qr  )*36 + k8+qc  ];
      a[1] = As[(m0+qr+8)*36 + k8+qc  ];
      a[2] = As[(m0+qr  )*36 + k8+qc+4];
      a[3] = As[(m0+qr+8)*36 + k8+qc+4];
      #pragma unroll
      for (int nt=0;nt<9;++nt) {
        uint32_t bfr[2];
        bfr[0] = T1g[(kc+k8+qc  )*72 + nt*8+qr];
        bfr[1] = T1g[(kc+k8+qc+4)*72 + nt*8+qr];
        mma1688(acc[nt], a, bfr);
      }
    }
  }
  __syncthreads();
  #pragma unroll
  for (int nt=0;nt<9;++nt) {
    int col = nt*8 + qc*2;
    B2[(m0+qr  )*72 + col  ] = f2tf32(acc[nt][0]);
    B2[(m0+qr  )*72 + col+1] = f2tf32(acc[nt][1]);
    B2[(m0+qr+8)*72 + col  ] = f2tf32(acc[nt][2]);
    B2[(m0+qr+8)*72 + col+1] = f2tf32(acc[nt][3]);
  }
  __syncthreads();

  // ---- GEMM2: O2 = T2 @ F ----
  #pragma unroll
  for (int nt=0;nt<9;++nt) {
    #pragma unroll
    for (int r=0;r<4;++r) acc[nt][r]=0.f;
  }
  #pragma unroll
  for (int ks2 = 0; ks2 < 16; ++ks2) {
    int k8 = ks2*8;
    uint32_t a[4];
    a[0] = T2g[(m0+qr  )*128 + k8+qc  ];
    a[1] = T2g[(m0+qr+8)*128 + k8+qc  ];
    a[2] = T2g[(m0+qr  )*128 + k8+qc+4];
    a[3] = T2g[(m0+qr+8)*128 + k8+qc+4];
    #pragma unroll
    for (int nt=0;nt<9;++nt) {
      uint32_t bfr[2];
      bfr[0] = B2[(k8+qc  )*72 + nt*8+qr];
      bfr[1] = B2[(k8+qc+4)*72 + nt*8+qr];
      mma1688(acc[nt], a, bfr);
    }
  }
  __syncthreads();
  #pragma unroll
  for (int nt=0;nt<9;++nt) {
    int col = nt*8 + qc*2;
    O2f[(m0+qr  )*72 + col  ] = acc[nt][0];
    O2f[(m0+qr  )*72 + col+1] = acc[nt][1];
    O2f[(m0+qr+8)*72 + col  ] = acc[nt][2];
    O2f[(m0+qr+8)*72 + col+1] = acc[nt][3];
  }
  __syncthreads();

  int n = c >> 6, i2 = c & 63;
  size_t zo = ((size_t)n*BSZ + i2)*NPTS + (size_t)b*2112;
  for (int idx = tid; idx < 2112; idx += 256) {
    int k = idx / 33, wf = idx % 33;
    float zr = (O2f[k*72 + wf] + O2f[(64+k)*72 + 33+wf]) * 0.0078125f;
    float zi = (O2f[k*72 + 33+wf] - O2f[(64+k)*72 + wf]) * 0.0078125f;
    g_Zr[zo + idx] = zr;
    g_Zi[zo + idx] = zi;
  }
}

// ---------------------------------------------------------------------------
// K3 (tf32 mma): complex MLP via real-stacked GEMMs.
// ---------------------------------------------------------------------------
__device__ __forceinline__ float gelu_f(float v) {
  return 0.5f*v*(1.0f + erff(v*0.70710678118654752f));
}
__device__ __forceinline__ float sshrink_f(float v) {
  float a = fabsf(v) - 0.01f;
  return a > 0.0f ? copysignf(a, v) : 0.0f;
}

__global__ __launch_bounds__(256) void k3_mma(
    const float* __restrict__ w1r, const float* __restrict__ w1i,
    const float* __restrict__ b1r, const float* __restrict__ b1i,
    const float* __restrict__ w2r, const float* __restrict__ w2i,
    const float* __restrict__ b2r, const float* __restrict__ b2i) {
  extern __shared__ float sm3f[];
  uint32_t* Asu = (uint32_t*)sm3f;          // [128 k][72 p]
  float*    Asf = sm3f;
  uint32_t* Bsu = (uint32_t*)sm3f + 9216;   // [32 k][136 n]
  float*    bs  = sm3f + 13568;
  int tid = threadIdx.x;
  int lane = tid & 31, wid = tid >> 5;
  int qr = lane >> 2, qc = lane & 3;
  int wm = (wid & 3) * 16;
  int wn = (wid >> 2) * 64;
  int bx = blockIdx.x;
  int nb = bx / 132, pt = bx % 132;
  size_t nbase = (size_t)nb*BSZ*NPTS + (size_t)pt*64;

  for (int idx = tid; idx < 4096; idx += 256) {
    int i = idx >> 6, p = idx & 63;
    Asu[i*72 + p]      = f2tf32(g_Zr[nbase + (size_t)i*NPTS + p]);
    Asu[(64+i)*72 + p] = f2tf32(g_Zi[nbase + (size_t)i*NPTS + p]);
  }
  if (tid < 64) {
    bs[tid]     = b1r[nb*64+tid]; bs[64+tid]  = b1i[nb*64+tid];
    bs[128+tid] = b2r[nb*64+tid]; bs[192+tid] = b2i[nb*64+tid];
  }

  float acc[8][4];

  #pragma unroll
  for (int layer = 0; layer < 2; ++layer) {
    const float* wr_ = layer ? w2r : w1r;
    const float* wi_ = layer ? w2i : w1i;
    #pragma unroll
    for (int nt=0;nt<8;++nt) {
      #pragma unroll
      for (int r=0;r<4;++r) acc[nt][r]=0.f;
    }
    for (int c0 = 0; c0 < 128; c0 += 32) {
      __syncthreads();
      #pragma unroll
      for (int it = 0; it < 4; ++it) {
        int slot = it*256 + tid;
        int kl = slot >> 5, c4 = slot & 31;
        int k = c0 + kl;
        float4 v; float sg = 1.f;
        if (k < 64) {
          if (c4 < 16) v = *(const float4*)&wr_[(size_t)nb*4096 + k*64 + c4*4];
          else         v = *(const float4*)&wi_[(size_t)nb*4096 + k*64 + (c4-16)*4];
        } else {
          int i = k - 64;
          if (c4 < 16) { v = *(const float4*)&wi_[(size_t)nb*4096 + i*64 + c4*4]; sg = -1.f; }
          else         v = *(const float4*)&wr_[(size_t)nb*4096 + i*64 + (c4-16)*4];
        }
        uint32_t* dst = &Bsu[kl*136 + c4*4];
        dst[0]=f2tf32(sg*v.x); dst[1]=f2tf32(sg*v.y);
        dst[2]=f2tf32(sg*v.z); dst[3]=f2tf32(sg*v.w);
      }
      __syncthreads();
      #pragma unroll
      for (int ks = 0; ks < 32; ks += 8) {
        uint32_t a[4];
        a[0] = Asu[(c0+ks+qc  )*72 + wm+qr  ];
        a[1] = Asu[(c0+ks+qc  )*72 + wm+qr+8];
        a[2] = Asu[(c0+ks+qc+4)*72 + wm+qr  ];
        a[3] = Asu[(c0+ks+qc+4)*72 + wm+qr+8];
        #pragma unroll
        for (int nt=0;nt<8;++nt) {
          uint32_t bfr[2];
          bfr[0] = Bsu[(ks+qc  )*136 + wn+nt*8+qr];
          bfr[1] = Bsu[(ks+qc+4)*136 + wn+nt*8+qr];
          mma1688(acc[nt], a, bfr);
        }
      }
    }
    __syncthreads();
    if (layer == 0) {
      #pragma unroll
      for (int nt=0;nt<8;++nt) {
        int j = wn + nt*8 + qc*2;
        Asu[(j  )*72 + wm+qr  ] = f2tf32(gelu_f(acc[nt][0] + bs[j  ]));
        Asu[(j+1)*72 + wm+qr  ] = f2tf32(gelu_f(acc[nt][1] + bs[j+1]));
        Asu[(j  )*72 + wm+qr+8] = f2tf32(gelu_f(acc[nt][2] + bs[j  ]));
        Asu[(j+1)*72 + wm+qr+8] = f2tf32(gelu_f(acc[nt][3] + bs[j+1]));
      }
    } else {
      #pragma unroll
      for (int nt=0;nt<8;++nt) {
        int j = wn + nt*8 + qc*2;
        Asf[(j  )*72 + wm+qr  ] = sshrink_f(acc[nt][0] + bs[128+j  ]);
        Asf[(j+1)*72 + wm+qr  ] = sshrink_f(acc[nt][1] + bs[128+j+1]);
        Asf[(j  )*72 + wm+qr+8] = sshrink_f(acc[nt][2] + bs[128+j  ]);
        Asf[(j+1)*72 + wm+qr+8] = sshrink_f(acc[nt][3] + bs[128+j+1]);
      }
    }
  }
  __syncthreads();
  for (int idx = tid; idx < 8192; idx += 256) {
    int j = idx >> 6, p = idx & 63;
    float y = Asf[j*72 + p];
    if (j < 64) {
      size_t o = nbase + (size_t)j*NPTS + p;
      g_Dr[o] = y - g_Zr[o];
    } else {
      size_t o = nbase + (size_t)(j-64)*NPTS + p;
      g_Di[o] = y - g_Zi[o];
    }
  }
}

// ---------------------------------------------------------------------------
// K45: fused inverse. T3/T4 fragments direct from gmem; smem = R only (38912 B)
// ---------------------------------------------------------------------------
__global__ __launch_bounds__(256) void k45_inv(const float* __restrict__ x) {
  extern __shared__ uint32_t smw[];
  uint32_t* R = smw;              // B3 [128][72] then G [128][76]

  int tid = threadIdx.x;
  int lane = tid & 31, wid = tid >> 5;
  int qr = lane >> 2, qc = lane & 3;
  int m0 = wid * 16;
  int bc = blockIdx.x;
  int b = bc >> 9, c = bc & 511;
  int n = c >> 6, i = c & 63;

  size_t dofs = ((size_t)n*BSZ + i)*NPTS + (size_t)b*2112;
  for (int idx = tid; idx < 2112; idx += 256) {
    int k = idx / 33, wf = idx % 33;
    float dr = g_Dr[dofs + idx], di = g_Di[dofs + idx];
    R[(k   )*72 + wf   ] = f2tf32(dr);
    R[(64+k)*72 + wf   ] = f2tf32(-di);
    R[(k   )*72 + 33+wf] = f2tf32(di);
    R[(64+k)*72 + 33+wf] = f2tf32(dr);
  }
  for (int idx = tid; idx < 128*6; idx += 256) {
    R[(idx/6)*72 + 66 + (idx % 6)] = 0u;
  }
  __syncthreads();

  // ---- GEMM3: G = T3 @ B3 ----
  float acc3[9][4];
  #pragma unroll
  for (int nt=0;nt<9;++nt) {
    #pragma unroll
    for (int r=0;r<4;++r) acc3[nt][r]=0.f;
  }
  #pragma unroll
  for (int ks3 = 0; ks3 < 16; ++ks3) {
    int k8 = ks3*8;
    uint32_t a[4];
    a[0] = T3g[(m0+qr  )*128 + k8+qc  ];
    a[1] = T3g[(m0+qr+8)*128 + k8+qc  ];
    a[2] = T3g[(m0+qr  )*128 + k8+qc+4];
    a[3] = T3g[(m0+qr+8)*128 + k8+qc+4];
    #pragma unroll
    for (int nt=0;nt<9;++nt) {
      uint32_t bfr[2];
      bfr[0] = R[(k8+qc  )*72 + nt*8+qr];
      bfr[1] = R[(k8+qc+4)*72 + nt*8+qr];
      mma1688(acc3[nt], a, bfr);
    }
  }
  __syncthreads();
  #pragma unroll
  for (int nt=0;nt<9;++nt) {
    int col = nt*8 + qc*2;
    R[(m0+qr  )*76 + col  ] = f2tf32(acc3[nt][0]);
    R[(m0+qr  )*76 + col+1] = f2tf32(acc3[nt][1]);
    R[(m0+qr+8)*76 + col  ] = f2tf32(acc3[nt][2]);
    R[(m0+qr+8)*76 + col+1] = f2tf32(acc3[nt][3]);
  }
  __syncthreads();

  // ---- GEMM4: S' = G @ T4 ----
  float acc4[16][4];
  #pragma unroll
  for (int nt=0;nt<16;++nt) {
    #pragma unroll
    for (int r=0;r<4;++r) acc4[nt][r]=0.f;
  }
  #pragma unroll
  for (int ks = 0; ks < 9; ++ks) {
    int k8 = ks*8;
    uint32_t a[4];
    a[0] = R[(m0+qr  )*76 + k8+qc  ];
    a[1] = R[(m0+qr+8)*76 + k8+qc  ];
    a[2] = R[(m0+qr  )*76 + k8+qc+4];
    a[3] = R[(m0+qr+8)*76 + k8+qc+4];
    #pragma unroll
    for (int nt=0;nt<16;++nt) {
      uint32_t bfr[2];
      bfr[0] = T4g[(k8+qc  )*136 + nt*8+qr];
      bfr[1] = T4g[(k8+qc+4)*136 + nt*8+qr];
      mma1688(acc4[nt], a, bfr);
    }
  }

  const float* xp = x + (size_t)bc*16384;
  float* Sp = g_S + (size_t)bc*16384;
  #pragma unroll
  for (int nt=0;nt<16;++nt) {
    int col = nt*8 + qc*2;
    int r0 = m0 + qr, r1 = m0 + qr + 8;
    float2 x0 = *(const float2*)&xp[r0*128 + col];
    float2 x1 = *(const float2*)&xp[r1*128 + col];
    float2 s0, s1;
    s0.x = x0.x + acc4[nt][0]; s0.y = x0.y + acc4[nt][1];
    s1.x = x1.x + acc4[nt][2]; s1.y = x1.y + acc4[nt][3];
    *(float2*)&Sp[r0*128 + col] = s0;
    *(float2*)&Sp[r1*128 + col] = s1;
  }
}

// ---------------------------------------------------------------------------
// K6: 256-o-row tiles, 512 threads, cp.async 2-stage
// ---------------------------------------------------------------------------
#define K6_A0 0
#define K6_A1 9216
#define K6_B0 18432
#define K6_B1 22784
#define K6_SMEM 108544

__device__ __forceinline__ void cpa16(uint32_t dst, const void* src) {
  asm volatile("cp.async.ca.shared.global [%0], [%1], 16;" :: "r"(dst), "l"(src));
}

__global__ __launch_bounds__(512) void k6_fuse_mma(const float* __restrict__ x,
                                                   const float* __restrict__ fw,
                                                   float* __restrict__ out) {
  extern __shared__ float sm6[];
  uint32_t smb;
  asm("{ .reg .u64 t; cvta.to.shared.u64 t, %1; cvt.u32.u64 %0, t; }"
      : "=r"(smb) : "l"(sm6));
  int tid = threadIdx.x;
  int lane = tid & 31, wid = tid >> 5;
  int bx = blockIdx.x;
  int hwT = (bx & 127) * 128;
  int t2 = bx >> 7;
  int oT = (t2 & 1) * 256;
  int b  = t2 >> 1;
  const float* Sb = g_S + (size_t)b*CC*16384;

  int wm = (wid & 7) * 32;
  int wn = (wid >> 3) * 64;
  int qr = lane >> 2;
  int qc = lane & 3;

  float acc[2][8][4];
  #pragma unroll
  for (int mt=0;mt<2;++mt) {
    #pragma unroll
    for (int nt=0;nt<8;++nt) {
      #pragma unroll
      for (int r=0;r<4;++r) acc[mt][nt][r]=0.f;
    }
  }

  auto load_chunk = [&](int ch) {
    int c0 = ch * 32;
    int aoff = (ch & 1) ? K6_A1 : K6_A0;
    int boff = (ch & 1) ? K6_B1 : K6_B0;
    #pragma unroll
    for (int it = 0; it < 4; ++it) {
      int slot = it*512 + tid;
      int o = slot >> 3, k4 = slot & 7;
      cpa16(smb + (uint32_t)(aoff + o*36 + k4*4)*4u,
            &fw[(size_t)(oT+o)*512 + c0 + k4*4]);
    }
    #pragma unroll
    for (int it = 0; it < 2; ++it) {
      int slot = it*512 + tid;
      int k = slot >> 5, h4 = slot & 31;
      cpa16(smb + (uint32_t)(boff + k*136 + h4*4)*4u,
            &Sb[(size_t)(c0+k)*16384 + hwT + h4*4]);
    }
    asm volatile("cp.async.commit_group;" ::: "memory");
  };

  load_chunk(0);
  for (int ch = 0; ch < 16; ++ch) {
    if (ch < 15) {
      load_chunk(ch + 1);
      asm volatile("cp.async.wait_group 1;" ::: "memory");
    } else {
      asm volatile("cp.async.wait_group 0;" ::: "memory");
    }
    __syncthreads();
    const float* Af = sm6 + ((ch & 1) ? K6_A1 : K6_A0);
    const float* Bf = sm6 + ((ch & 1) ? K6_B1 : K6_B0);
    #pragma unroll
    for (int ks = 0; ks < 32; ks += 8) {
      uint32_t afr[2][4];
      #pragma unroll
      for (int mt=0;mt<2;++mt) {
        int rb = wm + mt*16;
        afr[mt][0] = f2tf32(Af[(rb + qr     )*36 + ks + qc    ]);
        afr[mt][1] = f2tf32(Af[(rb + qr + 8 )*36 + ks + qc    ]);
        afr[mt][2] = f2tf32(Af[(rb + qr     )*36 + ks + qc + 4]);
        afr[mt][3] = f2tf32(Af[(rb + qr + 8 )*36 + ks + qc + 4]);
      }
      #pragma unroll
      for (int nt=0;nt<8;++nt) {
        int cb = wn + nt*8;
        uint32_t bfr[2];
        bfr[0] = f2tf32(Bf[(ks + qc    )*136 + cb + qr]);
        bfr[1] = f2tf32(Bf[(ks + qc + 4)*136 + cb + qr]);
        mma1688(acc[0][nt], afr[0], bfr);
        mma1688(acc[1][nt], afr[1], bfr);
      }
    }
    __syncthreads();
  }

  #pragma unroll
  for (int mt=0;mt<2;++mt) {
    int row0 = oT + wm + mt*16 + qr;
    #pragma unroll
    for (int nt=0;nt<8;++nt) {
      int col = hwT + wn + nt*8 + qc*2;
      size_t ob0 = ((size_t)(b*512 + row0    ))*16384 + col;
      size_t ob1 = ((size_t)(b*512 + row0 + 8))*16384 + col;
      float2 x0 = *(const float2*)&x[ob0];
      float2 x1 = *(const float2*)&x[ob1];
      float2 r0, r1;
      r0.x = x0.x + acc[mt][nt][0]; r0.y = x0.y + acc[mt][nt][1];
      r1.x = x1.x + acc[mt][nt][2]; r1.y = x1.y + acc[mt][nt][3];
      *(float2*)&out[ob0] = r0;
      *(float2*)&out[ob1] = r1;
    }
  }
}

// ---------------------------------------------------------------------------
extern "C" void kernel_launch(void* const* d_in, const int* in_sizes, int n_in,
                              void* d_out, int out_size) {
  const float* x   = (const float*)d_in[0];
  const float* w1r = (const float*)d_in[1];
  const float* w1i = (const float*)d_in[2];
  const float* b1r = (const float*)d_in[3];
  const float* b1i = (const float*)d_in[4];
  const float* w2r = (const float*)d_in[5];
  const float* w2i = (const float*)d_in[6];
  const float* b2r = (const float*)d_in[7];
  const float* b2i = (const float*)d_in[8];
  const float* fw  = (const float*)d_in[9];
  float* out = (float*)d_out;

  cudaFuncSetAttribute(k12_fwd, cudaFuncAttributeMaxDynamicSharedMemorySize, 55296);
  cudaFuncSetAttribute(k45_inv, cudaFuncAttributeMaxDynamicSharedMemorySize, 38912);
  cudaFuncSetAttribute(k3_mma,  cudaFuncAttributeMaxDynamicSharedMemorySize, 55296);
  cudaFuncSetAttribute(k6_fuse_mma, cudaFuncAttributeMaxDynamicSharedMemorySize, K6_SMEM);

  k0_twiddle<<<32, 256>>>();
  k12_fwd<<<BB*CC, 256, 55296>>>(x);
  k3_mma<<<NBK*132, 256, 55296>>>(w1r, w1i, b1r, b1i, w2r, w2i, b2r, b2i);
  k45_inv<<<BB*CC, 256, 38912>>>(x);
  k6_fuse_mma<<<BB*2*128, 512, K6_SMEM>>>(x, fw, out);
}

// round 15
// speedup vs baseline: 1.2408x; 1.2408x over previous
#include <cuda_runtime.h>
#include <math.h>
#include <stdint.h>

#define BB   4
#define CC   512
#define NBK  8
#define BSZ  64
#define WFM  33
#define KHM  64
#define NPTS (BB*KHM*WFM)     // 8448

// Z/D layout: [n][i][p]  (p = b*2112 + k*33 + wf) -> contiguous per image
__device__ float  g_Zr[NBK*BSZ*NPTS];
__device__ float  g_Zi[NBK*BSZ*NPTS];
__device__ float  g_Dr[NBK*BSZ*NPTS];
__device__ float  g_Di[NBK*BSZ*NPTS];
__device__ float  g_S[BB*CC*128*128];

__device__ uint32_t T1g[128*72];
__device__ uint32_t T2g[128*128];
__device__ uint32_t T3g[128*128];
__device__ uint32_t T4g[72*136];

__device__ __forceinline__ uint32_t f2tf32(float f) {
  uint32_t r; asm("cvt.rna.tf32.f32 %0, %1;" : "=r"(r) : "f"(f)); return r;
}
__device__ __forceinline__ void mma1688(float* d, const uint32_t* a, const uint32_t* b2) {
  asm volatile(
    "mma.sync.aligned.m16n8k8.row.col.f32.tf32.tf32.f32 "
    "{%0,%1,%2,%3}, {%4,%5,%6,%7}, {%8,%9}, {%0,%1,%2,%3};"
    : "+f"(d[0]), "+f"(d[1]), "+f"(d[2]), "+f"(d[3])
    : "r"(a[0]), "r"(a[1]), "r"(a[2]), "r"(a[3]), "r"(b2[0]), "r"(b2[1]));
}

// ---------------------------------------------------------------------------
__global__ __launch_bounds__(256) void k0_twiddle() {
  int tid = blockIdx.x*256 + threadIdx.x;
  for (int idx = tid; idx < 128*72; idx += 256*32) {
    int w = idx / 72, nf = idx % 72;
    float v = 0.f;
    if (nf < 33)      v =  cospif((float)((w*nf) & 127) * (1.0f/64.0f));
    else if (nf < 66) v = -sinpif((float)((w*(nf-33)) & 127) * (1.0f/64.0f));
    T1g[idx] = f2tf32(v);
  }
  for (int idx = tid; idx < 128*128; idx += 256*32) {
    int m = idx >> 7, h = idx & 127;
    float v = (m < 64) ? cospif((float)((h*m) & 127) * (1.0f/64.0f))
                       : sinpif((float)((h*(m-64)) & 127) * (1.0f/64.0f));
    T2g[idx] = f2tf32(v);
  }
  for (int idx = tid; idx < 128*128; idx += 256*32) {
    int h = idx >> 7, kk = idx & 127;
    float v = (kk < 64) ? cospif((float)((h*kk) & 127) * (1.0f/64.0f))
                        : sinpif((float)((h*(kk-64)) & 127) * (1.0f/64.0f));
    T3g[idx] = f2tf32(v);
  }
  for (int idx = tid; idx < 72*136; idx += 256*32) {
    int kk = idx / 136, w = idx % 136;
    float v = 0.f;
    if (w < 128) {
      if (kk == 0)       v = 1.0f/128.0f;
      else if (kk < 33)  v =  (1.0f/64.0f) * cospif((float)((w*kk) & 127) * (1.0f/64.0f));
      else if (kk == 33) v = 0.f;
      else if (kk < 66)  v = -(1.0f/64.0f) * sinpif((float)((w*(kk-33)) & 127) * (1.0f/64.0f));
    }
    T4g[idx] = f2tf32(v);
  }
}

// ---------------------------------------------------------------------------
// K12: fused forward. T1 staged CHUNK-WISE (9.2KB) -> smem 64.5KB, 2 CTA/SM.
// smem: As[128][36] | B2[128][72] | St[32][72]
// ---------------------------------------------------------------------------
__global__ __launch_bounds__(256) void k12_fwd(const float* __restrict__ x) {
  extern __shared__ uint32_t smw[];
  uint32_t* As = smw;            // [128][36]   x / T2 chunks
  uint32_t* B2 = smw + 4608;     // [128][72]   F tf32 / O2 fp32
  uint32_t* St = smw + 13824;    // [32][72]    T1 chunk
  float* O2f = (float*)B2;

  int tid = threadIdx.x;
  int lane = tid & 31, wid = tid >> 5;
  int qr = lane >> 2, qc = lane & 3;
  int m0 = wid * 16;
  int bc = blockIdx.x;
  int b = bc >> 9, c = bc & 511;
  const float* xp = x + (size_t)bc * 16384;

  // ---- GEMM1: F = x @ T1 ----
  float acc[9][4];
  #pragma unroll
  for (int nt=0;nt<9;++nt) {
    #pragma unroll
    for (int r=0;r<4;++r) acc[nt][r]=0.f;
  }
  for (int kc = 0; kc < 128; kc += 32) {
    __syncthreads();
    #pragma unroll
    for (int it = 0; it < 16; ++it) {
      int s = it*256 + tid;
      int h = s >> 5, w = s & 31;
      As[h*36 + w] = f2tf32(xp[h*128 + kc + w]);
    }
    #pragma unroll
    for (int it = 0; it < 9; ++it) {
      int s = it*256 + tid;
      if (s < 2304) St[s] = T1g[kc*72 + s];
    }
    __syncthreads();
    #pragma unroll
    for (int ks = 0; ks < 4; ++ks) {
      int k8 = ks*8;
      uint32_t a[4];
      a[0] = As[(m0+qr  )*36 + k8+qc  ];
      a[1] = As[(m0+qr+8)*36 + k8+qc  ];
      a[2] = As[(m0+qr  )*36 + k8+qc+4];
      a[3] = As[(m0+qr+8)*36 + k8+qc+4];
      #pragma unroll
      for (int nt=0;nt<9;++nt) {
        uint32_t bfr[2];
        bfr[0] = St[(k8+qc  )*72 + nt*8+qr];
        bfr[1] = St[(k8+qc+4)*72 + nt*8+qr];
        mma1688(acc[nt], a, bfr);
      }
    }
  }
  __syncthreads();
  #pragma unroll
  for (int nt=0;nt<9;++nt) {
    int col = nt*8 + qc*2;
    B2[(m0+qr  )*72 + col  ] = f2tf32(acc[nt][0]);
    B2[(m0+qr  )*72 + col+1] = f2tf32(acc[nt][1]);
    B2[(m0+qr+8)*72 + col  ] = f2tf32(acc[nt][2]);
    B2[(m0+qr+8)*72 + col+1] = f2tf32(acc[nt][3]);
  }

  // ---- GEMM2: O2 = T2 @ F (T2 chunks staged into As) ----
  #pragma unroll
  for (int nt=0;nt<9;++nt) {
    #pragma unroll
    for (int r=0;r<4;++r) acc[nt][r]=0.f;
  }
  for (int kc = 0; kc < 128; kc += 32) {
    __syncthreads();
    #pragma unroll
    for (int it = 0; it < 16; ++it) {
      int s = it*256 + tid;
      int m = s >> 5, h = s & 31;
      As[m*36 + h] = T2g[m*128 + kc + h];
    }
    __syncthreads();
    #pragma unroll
    for (int ks = 0; ks < 4; ++ks) {
      int k8 = ks*8;
      uint32_t a[4];
      a[0] = As[(m0+qr  )*36 + k8+qc  ];
      a[1] = As[(m0+qr+8)*36 + k8+qc  ];
      a[2] = As[(m0+qr  )*36 + k8+qc+4];
      a[3] = As[(m0+qr+8)*36 + k8+qc+4];
      #pragma unroll
      for (int nt=0;nt<9;++nt) {
        uint32_t bfr[2];
        bfr[0] = B2[(kc+k8+qc  )*72 + nt*8+qr];
        bfr[1] = B2[(kc+k8+qc+4)*72 + nt*8+qr];
        mma1688(acc[nt], a, bfr);
      }
    }
  }
  __syncthreads();
  #pragma unroll
  for (int nt=0;nt<9;++nt) {
    int col = nt*8 + qc*2;
    O2f[(m0+qr  )*72 + col  ] = acc[nt][0];
    O2f[(m0+qr  )*72 + col+1] = acc[nt][1];
    O2f[(m0+qr+8)*72 + col  ] = acc[nt][2];
    O2f[(m0+qr+8)*72 + col+1] = acc[nt][3];
  }
  __syncthreads();

  int n = c >> 6, i2 = c & 63;
  size_t zo = ((size_t)n*BSZ + i2)*NPTS + (size_t)b*2112;
  for (int idx = tid; idx < 2112; idx += 256) {
    int k = idx / 33, wf = idx % 33;
    float zr = (O2f[k*72 + wf] + O2f[(64+k)*72 + 33+wf]) * 0.0078125f;
    float zi = (O2f[k*72 + 33+wf] - O2f[(64+k)*72 + wf]) * 0.0078125f;
    g_Zr[zo + idx] = zr;
    g_Zi[zo + idx] = zi;
  }
}

// ---------------------------------------------------------------------------
// K3 (tf32 mma): complex MLP via real-stacked GEMMs.  (unchanged from R11)
// ---------------------------------------------------------------------------
__device__ __forceinline__ float gelu_f(float v) {
  return 0.5f*v*(1.0f + erff(v*0.70710678118654752f));
}
__device__ __forceinline__ float sshrink_f(float v) {
  float a = fabsf(v) - 0.01f;
  return a > 0.0f ? copysignf(a, v) : 0.0f;
}

__global__ __launch_bounds__(256) void k3_mma(
    const float* __restrict__ w1r, const float* __restrict__ w1i,
    const float* __restrict__ b1r, const float* __restrict__ b1i,
    const float* __restrict__ w2r, const float* __restrict__ w2i,
    const float* __restrict__ b2r, const float* __restrict__ b2i) {
  extern __shared__ float sm3f[];
  uint32_t* Asu = (uint32_t*)sm3f;          // [128 k][72 p]
  float*    Asf = sm3f;
  uint32_t* Bsu = (uint32_t*)sm3f + 9216;   // [32 k][136 n]
  float*    bs  = sm3f + 13568;
  int tid = threadIdx.x;
  int lane = tid & 31, wid = tid >> 5;
  int qr = lane >> 2, qc = lane & 3;
  int wm = (wid & 3) * 16;
  int wn = (wid >> 2) * 64;
  int bx = blockIdx.x;
  int nb = bx / 132, pt = bx % 132;
  size_t nbase = (size_t)nb*BSZ*NPTS + (size_t)pt*64;

  for (int idx = tid; idx < 4096; idx += 256) {
    int i = idx >> 6, p = idx & 63;
    Asu[i*72 + p]      = f2tf32(g_Zr[nbase + (size_t)i*NPTS + p]);
    Asu[(64+i)*72 + p] = f2tf32(g_Zi[nbase + (size_t)i*NPTS + p]);
  }
  if (tid < 64) {
    bs[tid]     = b1r[nb*64+tid]; bs[64+tid]  = b1i[nb*64+tid];
    bs[128+tid] = b2r[nb*64+tid]; bs[192+tid] = b2i[nb*64+tid];
  }

  float acc[8][4];

  #pragma unroll
  for (int layer = 0; layer < 2; ++layer) {
    const float* wr_ = layer ? w2r : w1r;
    const float* wi_ = layer ? w2i : w1i;
    #pragma unroll
    for (int nt=0;nt<8;++nt) {
      #pragma unroll
      for (int r=0;r<4;++r) acc[nt][r]=0.f;
    }
    for (int c0 = 0; c0 < 128; c0 += 32) {
      __syncthreads();
      #pragma unroll
      for (int it = 0; it < 4; ++it) {
        int slot = it*256 + tid;
        int kl = slot >> 5, c4 = slot & 31;
        int k = c0 + kl;
        float4 v; float sg = 1.f;
        if (k < 64) {
          if (c4 < 16) v = *(const float4*)&wr_[(size_t)nb*4096 + k*64 + c4*4];
          else         v = *(const float4*)&wi_[(size_t)nb*4096 + k*64 + (c4-16)*4];
        } else {
          int i = k - 64;
          if (c4 < 16) { v = *(const float4*)&wi_[(size_t)nb*4096 + i*64 + c4*4]; sg = -1.f; }
          else         v = *(const float4*)&wr_[(size_t)nb*4096 + i*64 + (c4-16)*4];
        }
        uint32_t* dst = &Bsu[kl*136 + c4*4];
        dst[0]=f2tf32(sg*v.x); dst[1]=f2tf32(sg*v.y);
        dst[2]=f2tf32(sg*v.z); dst[3]=f2tf32(sg*v.w);
      }
      __syncthreads();
      #pragma unroll
      for (int ks = 0; ks < 32; ks += 8) {
        uint32_t a[4];
        a[0] = Asu[(c0+ks+qc  )*72 + wm+qr  ];
        a[1] = Asu[(c0+ks+qc  )*72 + wm+qr+8];
        a[2] = Asu[(c0+ks+qc+4)*72 + wm+qr  ];
        a[3] = Asu[(c0+ks+qc+4)*72 + wm+qr+8];
        #pragma unroll
        for (int nt=0;nt<8;++nt) {
          uint32_t bfr[2];
          bfr[0] = Bsu[(ks+qc  )*136 + wn+nt*8+qr];
          bfr[1] = Bsu[(ks+qc+4)*136 + wn+nt*8+qr];
          mma1688(acc[nt], a, bfr);
        }
      }
    }
    __syncthreads();
    if (layer == 0) {
      #pragma unroll
      for (int nt=0;nt<8;++nt) {
        int j = wn + nt*8 + qc*2;
        Asu[(j  )*72 + wm+qr  ] = f2tf32(gelu_f(acc[nt][0] + bs[j  ]));
        Asu[(j+1)*72 + wm+qr  ] = f2tf32(gelu_f(acc[nt][1] + bs[j+1]));
        Asu[(j  )*72 + wm+qr+8] = f2tf32(gelu_f(acc[nt][2] + bs[j  ]));
        Asu[(j+1)*72 + wm+qr+8] = f2tf32(gelu_f(acc[nt][3] + bs[j+1]));
      }
    } else {
      #pragma unroll
      for (int nt=0;nt<8;++nt) {
        int j = wn + nt*8 + qc*2;
        Asf[(j  )*72 + wm+qr  ] = sshrink_f(acc[nt][0] + bs[128+j  ]);
        Asf[(j+1)*72 + wm+qr  ] = sshrink_f(acc[nt][1] + bs[128+j+1]);
        Asf[(j  )*72 + wm+qr+8] = sshrink_f(acc[nt][2] + bs[128+j  ]);
        Asf[(j+1)*72 + wm+qr+8] = sshrink_f(acc[nt][3] + bs[128+j+1]);
      }
    }
  }
  __syncthreads();
  for (int idx = tid; idx < 8192; idx += 256) {
    int j = idx >> 6, p = idx & 63;
    float y = Asf[j*72 + p];
    if (j < 64) {
      size_t o = nbase + (size_t)j*NPTS + p;
      g_Dr[o] = y - g_Zr[o];
    } else {
      size_t o = nbase + (size_t)(j-64)*NPTS + p;
      g_Di[o] = y - g_Zi[o];
    }
  }
}

// ---------------------------------------------------------------------------
// K45: fused inverse. T3 staged chunk-wise (as R11); T4 staged CHUNK-WISE
// (8 rows / 4.3KB per GEMM4 step) -> smem 61.7KB, 2 CTA/SM.
// smem: R[128][76] | As[128][36] | St[8][136]
// ---------------------------------------------------------------------------
__global__ __launch_bounds__(256) void k45_inv(const float* __restrict__ x) {
  extern __shared__ uint32_t smw[];
  uint32_t* R  = smw;             // B3 [128][72] then G [128][76]
  uint32_t* As = smw + 9728;      // [128][36]
  uint32_t* St = smw + 14336;     // [8][136]

  int tid = threadIdx.x;
  int lane = tid & 31, wid = tid >> 5;
  int qr = lane >> 2, qc = lane & 3;
  int m0 = wid * 16;
  int bc = blockIdx.x;
  int b = bc >> 9, c = bc & 511;
  int n = c >> 6, i = c & 63;

  size_t dofs = ((size_t)n*BSZ + i)*NPTS + (size_t)b*2112;
  for (int idx = tid; idx < 2112; idx += 256) {
    int k = idx / 33, wf = idx % 33;
    float dr = g_Dr[dofs + idx], di = g_Di[dofs + idx];
    R[(k   )*72 + wf   ] = f2tf32(dr);
    R[(64+k)*72 + wf   ] = f2tf32(-di);
    R[(k   )*72 + 33+wf] = f2tf32(di);
    R[(64+k)*72 + 33+wf] = f2tf32(dr);
  }
  for (int idx = tid; idx < 128*6; idx += 256) {
    R[(idx/6)*72 + 66 + (idx % 6)] = 0u;
  }

  // ---- GEMM3: G = T3 @ B3, T3 chunks staged into As ----
  float acc3[9][4];
  #pragma unroll
  for (int nt=0;nt<9;++nt) {
    #pragma unroll
    for (int r=0;r<4;++r) acc3[nt][r]=0.f;
  }
  for (int kc = 0; kc < 128; kc += 32) {
    __syncthreads();
    #pragma unroll
    for (int it = 0; it < 16; ++it) {
      int s = it*256 + tid;
      int h = s >> 5, kl = s & 31;
      As[h*36 + kl] = T3g[h*128 + kc + kl];
    }
    __syncthreads();
    #pragma unroll
    for (int ks = 0; ks < 4; ++ks) {
      int k8 = ks*8;
      uint32_t a[4];
      a[0] = As[(m0+qr  )*36 + k8+qc  ];
      a[1] = As[(m0+qr+8)*36 + k8+qc  ];
      a[2] = As[(m0+qr  )*36 + k8+qc+4];
      a[3] = As[(m0+qr+8)*36 + k8+qc+4];
      #pragma unroll
      for (int nt=0;nt<9;++nt) {
        uint32_t bfr[2];
        bfr[0] = R[(kc+k8+qc  )*72 + nt*8+qr];
        bfr[1] = R[(kc+k8+qc+4)*72 + nt*8+qr];
        mma1688(acc3[nt], a, bfr);
      }
    }
  }
  __syncthreads();
  #pragma unroll
  for (int nt=0;nt<9;++nt) {
    int col = nt*8 + qc*2;
    R[(m0+qr  )*76 + col  ] = f2tf32(acc3[nt][0]);
    R[(m0+qr  )*76 + col+1] = f2tf32(acc3[nt][1]);
    R[(m0+qr+8)*76 + col  ] = f2tf32(acc3[nt][2]);
    R[(m0+qr+8)*76 + col+1] = f2tf32(acc3[nt][3]);
  }

  // ---- GEMM4: S' = G @ T4, T4 staged 8 rows at a time ----
  float acc4[16][4];
  #pragma unroll
  for (int nt=0;nt<16;++nt) {
    #pragma unroll
    for (int r=0;r<4;++r) acc4[nt][r]=0.f;
  }
  #pragma unroll
  for (int ks = 0; ks < 9; ++ks) {
    int k8 = ks*8;
    __syncthreads();
    #pragma unroll
    for (int it = 0; it < 5; ++it) {
      int s = it*256 + tid;
      if (s < 1088) St[s] = T4g[k8*136 + s];
    }
    __syncthreads();
    uint32_t a[4];
    a[0] = R[(m0+qr  )*76 + k8+qc  ];
    a[1] = R[(m0+qr+8)*76 + k8+qc  ];
    a[2] = R[(m0+qr  )*76 + k8+qc+4];
    a[3] = R[(m0+qr+8)*76 + k8+qc+4];
    #pragma unroll
    for (int nt=0;nt<16;++nt) {
      uint32_t bfr[2];
      bfr[0] = St[(qc  )*136 + nt*8+qr];
      bfr[1] = St[(qc+4)*136 + nt*8+qr];
      mma1688(acc4[nt], a, bfr);
    }
  }

  const float* xp = x + (size_t)bc*16384;
  float* Sp = g_S + (size_t)bc*16384;
  #pragma unroll
  for (int nt=0;nt<16;++nt) {
    int col = nt*8 + qc*2;
    int r0 = m0 + qr, r1 = m0 + qr + 8;
    float2 x0 = *(const float2*)&xp[r0*128 + col];
    float2 x1 = *(const float2*)&xp[r1*128 + col];
    float2 s0, s1;
    s0.x = x0.x + acc4[nt][0]; s0.y = x0.y + acc4[nt][1];
    s1.x = x1.x + acc4[nt][2]; s1.y = x1.y + acc4[nt][3];
    *(float2*)&Sp[r0*128 + col] = s0;
    *(float2*)&Sp[r1*128 + col] = s1;
  }
}

// ---------------------------------------------------------------------------
// K6: 256-o-row tiles, 512 threads, cp.async 2-stage  (unchanged from R11)
// ---------------------------------------------------------------------------
#define K6_A0 0
#define K6_A1 9216
#define K6_B0 18432
#define K6_B1 22784
#define K6_SMEM 108544

__device__ __forceinline__ void cpa16(uint32_t dst, const void* src) {
  asm volatile("cp.async.ca.shared.global [%0], [%1], 16;" :: "r"(dst), "l"(src));
}

__global__ __launch_bounds__(512) void k6_fuse_mma(const float* __restrict__ x,
                                                   const float* __restrict__ fw,
                                                   float* __restrict__ out) {
  extern __shared__ float sm6[];
  uint32_t smb;
  asm("{ .reg .u64 t; cvta.to.shared.u64 t, %1; cvt.u32.u64 %0, t; }"
      : "=r"(smb) : "l"(sm6));
  int tid = threadIdx.x;
  int lane = tid & 31, wid = tid >> 5;
  int bx = blockIdx.x;
  int hwT = (bx & 127) * 128;
  int t2 = bx >> 7;
  int oT = (t2 & 1) * 256;
  int b  = t2 >> 1;
  const float* Sb = g_S + (size_t)b*CC*16384;

  int wm = (wid & 7) * 32;
  int wn = (wid >> 3) * 64;
  int qr = lane >> 2;
  int qc = lane & 3;

  float acc[2][8][4];
  #pragma unroll
  for (int mt=0;mt<2;++mt) {
    #pragma unroll
    for (int nt=0;nt<8;++nt) {
      #pragma unroll
      for (int r=0;r<4;++r) acc[mt][nt][r]=0.f;
    }
  }

  auto load_chunk = [&](int ch) {
    int c0 = ch * 32;
    int aoff = (ch & 1) ? K6_A1 : K6_A0;
    int boff = (ch & 1) ? K6_B1 : K6_B0;
    #pragma unroll
    for (int it = 0; it < 4; ++it) {
      int slot = it*512 + tid;
      int o = slot >> 3, k4 = slot & 7;
      cpa16(smb + (uint32_t)(aoff + o*36 + k4*4)*4u,
            &fw[(size_t)(oT+o)*512 + c0 + k4*4]);
    }
    #pragma unroll
    for (int it = 0; it < 2; ++it) {
      int slot = it*512 + tid;
      int k = slot >> 5, h4 = slot & 31;
      cpa16(smb + (uint32_t)(boff + k*136 + h4*4)*4u,
            &Sb[(size_t)(c0+k)*16384 + hwT + h4*4]);
    }
    asm volatile("cp.async.commit_group;" ::: "memory");
  };

  load_chunk(0);
  for (int ch = 0; ch < 16; ++ch) {
    if (ch < 15) {
      load_chunk(ch + 1);
      asm volatile("cp.async.wait_group 1;" ::: "memory");
    } else {
      asm volatile("cp.async.wait_group 0;" ::: "memory");
    }
    __syncthreads();
    const float* Af = sm6 + ((ch & 1) ? K6_A1 : K6_A0);
    const float* Bf = sm6 + ((ch & 1) ? K6_B1 : K6_B0);
    #pragma unroll
    for (int ks = 0; ks < 32; ks += 8) {
      uint32_t afr[2][4];
      #pragma unroll
      for (int mt=0;mt<2;++mt) {
        int rb = wm + mt*16;
        afr[mt][0] = f2tf32(Af[(rb + qr     )*36 + ks + qc    ]);
        afr[mt][1] = f2tf32(Af[(rb + qr + 8 )*36 + ks + qc    ]);
        afr[mt][2] = f2tf32(Af[(rb + qr     )*36 + ks + qc + 4]);
        afr[mt][3] = f2tf32(Af[(rb + qr + 8 )*36 + ks + qc + 4]);
      }
      #pragma unroll
      for (int nt=0;nt<8;++nt) {
        int cb = wn + nt*8;
        uint32_t bfr[2];
        bfr[0] = f2tf32(Bf[(ks + qc    )*136 + cb + qr]);
        bfr[1] = f2tf32(Bf[(ks + qc + 4)*136 + cb + qr]);
        mma1688(acc[0][nt], afr[0], bfr);
        mma1688(acc[1][nt], afr[1], bfr);
      }
    }
    __syncthreads();
  }

  #pragma unroll
  for (int mt=0;mt<2;++mt) {
    int row0 = oT + wm + mt*16 + qr;
    #pragma unroll
    for (int nt=0;nt<8;++nt) {
      int col = hwT + wn + nt*8 + qc*2;
      size_t ob0 = ((size_t)(b*512 + row0    ))*16384 + col;
      size_t ob1 = ((size_t)(b*512 + row0 + 8))*16384 + col;
      float2 x0 = *(const float2*)&x[ob0];
      float2 x1 = *(const float2*)&x[ob1];
      float2 r0, r1;
      r0.x = x0.x + acc[mt][nt][0]; r0.y = x0.y + acc[mt][nt][1];
      r1.x = x1.x + acc[mt][nt][2]; r1.y = x1.y + acc[mt][nt][3];
      *(float2*)&out[ob0] = r0;
      *(float2*)&out[ob1] = r1;
    }
  }
}

// ---------------------------------------------------------------------------
extern "C" void kernel_launch(void* const* d_in, const int* in_sizes, int n_in,
                              void* d_out, int out_size) {
  const float* x   = (const float*)d_in[0];
  const float* w1r = (const float*)d_in[1];
  const float* w1i = (const float*)d_in[2];
  const float* b1r = (const float*)d_in[3];
  const float* b1i = (const float*)d_in[4];
  const float* w2r = (const float*)d_in[5];
  const float* w2i = (const float*)d_in[6];
  const float* b2r = (const float*)d_in[7];
  const float* b2i = (const float*)d_in[8];
  const float* fw  = (const float*)d_in[9];
  float* out = (float*)d_out;

  cudaFuncSetAttribute(k12_fwd, cudaFuncAttributeMaxDynamicSharedMemorySize, 64512);
  cudaFuncSetAttribute(k45_inv, cudaFuncAttributeMaxDynamicSharedMemorySize, 61696);
  cudaFuncSetAttribute(k3_mma,  cudaFuncAttributeMaxDynamicSharedMemorySize, 55296);
  cudaFuncSetAttribute(k6_fuse_mma, cudaFuncAttributeMaxDynamicSharedMemorySize, K6_SMEM);

  k0_twiddle<<<32, 256>>>();
  k12_fwd<<<BB*CC, 256, 64512>>>(x);
  k3_mma<<<NBK*132, 256, 55296>>>(w1r, w1i, b1r, b1i, w2r, w2i, b2r, b2i);
  k45_inv<<<BB*CC, 256, 61696>>>(x);
  k6_fuse_mma<<<BB*2*128, 512, K6_SMEM>>>(x, fw, out);
}

// round 16
// speedup vs baseline: 1.3395x; 1.0795x over previous
#include <cuda_runtime.h>
#include <math.h>
#include <stdint.h>

#define BB   4
#define CC   512
#define NBK  8
#define BSZ  64
#define WFM  33
#define KHM  64
#define NPTS (BB*KHM*WFM)     // 8448

// Z/D layout: [n][i][p]  (p = b*2112 + k*33 + wf)
__device__ float  g_Zr[NBK*BSZ*NPTS];
__device__ float  g_Zi[NBK*BSZ*NPTS];
__device__ float  g_Dr[NBK*BSZ*NPTS];
__device__ float  g_Di[NBK*BSZ*NPTS];
__device__ float  g_S[BB*CC*128*128];

__device__ uint32_t T1g[128*72];
__device__ uint32_t T2g[128*128];
__device__ uint32_t T3g[128*128];
__device__ uint32_t T4g[72*136];

__device__ __forceinline__ uint32_t f2tf32(float f) {
  uint32_t r; asm("cvt.rna.tf32.f32 %0, %1;" : "=r"(r) : "f"(f)); return r;
}
__device__ __forceinline__ void mma1688(float* d, const uint32_t* a, const uint32_t* b2) {
  asm volatile(
    "mma.sync.aligned.m16n8k8.row.col.f32.tf32.tf32.f32 "
    "{%0,%1,%2,%3}, {%4,%5,%6,%7}, {%8,%9}, {%0,%1,%2,%3};"
    : "+f"(d[0]), "+f"(d[1]), "+f"(d[2]), "+f"(d[3])
    : "r"(a[0]), "r"(a[1]), "r"(a[2]), "r"(a[3]), "r"(b2[0]), "r"(b2[1]));
}
__device__ __forceinline__ void cpa16(uint32_t dst, const void* src) {
  asm volatile("cp.async.ca.shared.global [%0], [%1], 16;" :: "r"(dst), "l"(src));
}
__device__ __forceinline__ void cpa_commit() {
  asm volatile("cp.async.commit_group;" ::: "memory");
}
__device__ __forceinline__ void cpa_wait1() {
  asm volatile("cp.async.wait_group 1;" ::: "memory");
}
__device__ __forceinline__ void cpa_wait0() {
  asm volatile("cp.async.wait_group 0;" ::: "memory");
}
__device__ __forceinline__ uint32_t smaddr(const void* p) {
  uint32_t a;
  asm("{ .reg .u64 t; cvta.to.shared.u64 t, %1; cvt.u32.u64 %0, t; }" : "=r"(a) : "l"(p));
  return a;
}

// ---------------------------------------------------------------------------
__global__ __launch_bounds__(256) void k0_twiddle() {
  int tid = blockIdx.x*256 + threadIdx.x;
  for (int idx = tid; idx < 128*72; idx += 256*32) {
    int w = idx / 72, nf = idx % 72;
    float v = 0.f;
    if (nf < 33)      v =  cospif((float)((w*nf) & 127) * (1.0f/64.0f));
    else if (nf < 66) v = -sinpif((float)((w*(nf-33)) & 127) * (1.0f/64.0f));
    T1g[idx] = f2tf32(v);
  }
  for (int idx = tid; idx < 128*128; idx += 256*32) {
    int m = idx >> 7, h = idx & 127;
    float v = (m < 64) ? cospif((float)((h*m) & 127) * (1.0f/64.0f))
                       : sinpif((float)((h*(m-64)) & 127) * (1.0f/64.0f));
    T2g[idx] = f2tf32(v);
  }
  for (int idx = tid; idx < 128*128; idx += 256*32) {
    int h = idx >> 7, kk = idx & 127;
    float v = (kk < 64) ? cospif((float)((h*kk) & 127) * (1.0f/64.0f))
                        : sinpif((float)((h*(kk-64)) & 127) * (1.0f/64.0f));
    T3g[idx] = f2tf32(v);
  }
  for (int idx = tid; idx < 72*136; idx += 256*32) {
    int kk = idx / 136, w = idx % 136;
    float v = 0.f;
    if (w < 128) {
      if (kk == 0)       v = 1.0f/128.0f;
      else if (kk < 33)  v =  (1.0f/64.0f) * cospif((float)((w*kk) & 127) * (1.0f/64.0f));
      else if (kk == 33) v = 0.f;
      else if (kk < 66)  v = -(1.0f/64.0f) * sinpif((float)((w*(kk-33)) & 127) * (1.0f/64.0f));
    }
    T4g[idx] = f2tf32(v);
  }
}

// ---------------------------------------------------------------------------
// K12: fused forward, cp.async double-buffered staging.
// smem uint32: A0[4608] A1[4608] St0[2304] St1[2304] B2[9216] = 92160 B
// ---------------------------------------------------------------------------
#define K12_A0 0
#define K12_A1 4608
#define K12_S0 9216
#define K12_S1 11520
#define K12_B2 13824
#define K12_SMEM 92160

__global__ __launch_bounds__(256) void k12_fwd(const float* __restrict__ x) {
  extern __shared__ uint32_t smw[];
  uint32_t smb = smaddr(smw);
  uint32_t* B2 = smw + K12_B2;
  float* O2f = (float*)B2;

  int tid = threadIdx.x;
  int lane = tid & 31, wid = tid >> 5;
  int qr = lane >> 2, qc = lane & 3;
  int m0 = wid * 16;
  int bc = blockIdx.x;
  int b = bc >> 9, c = bc & 511;
  const float* xp = x + (size_t)bc * 16384;

  // ---- GEMM1: F = x @ T1, pipelined ----
  float acc[9][4];
  #pragma unroll
  for (int nt=0;nt<9;++nt) {
    #pragma unroll
    for (int r=0;r<4;++r) acc[nt][r]=0.f;
  }

  auto load1 = [&](int ch) {
    int kc = ch * 32;
    uint32_t ab = smb + ((ch & 1) ? K12_A1 : K12_A0)*4u;
    uint32_t sb = smb + ((ch & 1) ? K12_S1 : K12_S0)*4u;
    #pragma unroll
    for (int it = 0; it < 4; ++it) {       // x: 1024 float4
      int s = it*256 + tid;
      int h = s >> 3, k4 = s & 7;
      cpa16(ab + (uint32_t)(h*36 + k4*4)*4u, &xp[h*128 + kc + k4*4]);
    }
    #pragma unroll
    for (int it = 0; it < 3; ++it) {       // T1 chunk: 576 float4
      int s = it*256 + tid;
      if (s < 576) cpa16(sb + (uint32_t)s*16u, &T1g[kc*72 + s*4]);
    }
    cpa_commit();
  };

  load1(0);
  for (int ch = 0; ch < 4; ++ch) {
    if (ch < 3) { load1(ch + 1); cpa_wait1(); } else { cpa_wait0(); }
    __syncthreads();
    const float* Af = (const float*)(smw + ((ch & 1) ? K12_A1 : K12_A0));
    const uint32_t* St = smw + ((ch & 1) ? K12_S1 : K12_S0);
    #pragma unroll
    for (int ks = 0; ks < 4; ++ks) {
      int k8 = ks*8;
      uint32_t a[4];
      a[0] = f2tf32(Af[(m0+qr  )*36 + k8+qc  ]);
      a[1] = f2tf32(Af[(m0+qr+8)*36 + k8+qc  ]);
      a[2] = f2tf32(Af[(m0+qr  )*36 + k8+qc+4]);
      a[3] = f2tf32(Af[(m0+qr+8)*36 + k8+qc+4]);
      #pragma unroll
      for (int nt=0;nt<9;++nt) {
        uint32_t bfr[2];
        bfr[0] = St[(k8+qc  )*72 + nt*8+qr];
        bfr[1] = St[(k8+qc+4)*72 + nt*8+qr];
        mma1688(acc[nt], a, bfr);
      }
    }
    __syncthreads();
  }
  #pragma unroll
  for (int nt=0;nt<9;++nt) {
    int col = nt*8 + qc*2;
    B2[(m0+qr  )*72 + col  ] = f2tf32(acc[nt][0]);
    B2[(m0+qr  )*72 + col+1] = f2tf32(acc[nt][1]);
    B2[(m0+qr+8)*72 + col  ] = f2tf32(acc[nt][2]);
    B2[(m0+qr+8)*72 + col+1] = f2tf32(acc[nt][3]);
  }

  // ---- GEMM2: O2 = T2 @ F, pipelined (T2 chunks in A buffers) ----
  #pragma unroll
  for (int nt=0;nt<9;++nt) {
    #pragma unroll
    for (int r=0;r<4;++r) acc[nt][r]=0.f;
  }
  auto load2 = [&](int ch) {
    int kc = ch * 32;
    uint32_t ab = smb + ((ch & 1) ? K12_A1 : K12_A0)*4u;
    #pragma unroll
    for (int it = 0; it < 4; ++it) {       // T2 chunk: 1024 float4
      int s = it*256 + tid;
      int m = s >> 3, k4 = s & 7;
      cpa16(ab + (uint32_t)(m*36 + k4*4)*4u, &T2g[m*128 + kc + k4*4]);
    }
    cpa_commit();
  };
  load2(0);
  for (int ch = 0; ch < 4; ++ch) {
    if (ch < 3) { load2(ch + 1); cpa_wait1(); } else { cpa_wait0(); }
    __syncthreads();
    int kc = ch * 32;
    const uint32_t* At = smw + ((ch & 1) ? K12_A1 : K12_A0);
    #pragma unroll
    for (int ks = 0; ks < 4; ++ks) {
      int k8 = ks*8;
      uint32_t a[4];
      a[0] = At[(m0+qr  )*36 + k8+qc  ];
      a[1] = At[(m0+qr+8)*36 + k8+qc  ];
      a[2] = At[(m0+qr  )*36 + k8+qc+4];
      a[3] = At[(m0+qr+8)*36 + k8+qc+4];
      #pragma unroll
      for (int nt=0;nt<9;++nt) {
        uint32_t bfr[2];
        bfr[0] = B2[(kc+k8+qc  )*72 + nt*8+qr];
        bfr[1] = B2[(kc+k8+qc+4)*72 + nt*8+qr];
        mma1688(acc[nt], a, bfr);
      }
    }
    __syncthreads();
  }
  #pragma unroll
  for (int nt=0;nt<9;++nt) {
    int col = nt*8 + qc*2;
    O2f[(m0+qr  )*72 + col  ] = acc[nt][0];
    O2f[(m0+qr  )*72 + col+1] = acc[nt][1];
    O2f[(m0+qr+8)*72 + col  ] = acc[nt][2];
    O2f[(m0+qr+8)*72 + col+1] = acc[nt][3];
  }
  __syncthreads();

  int n = c >> 6, i2 = c & 63;
  size_t zo = ((size_t)n*BSZ + i2)*NPTS + (size_t)b*2112;
  for (int idx = tid; idx < 2112; idx += 256) {
    int k = idx / 33, wf = idx % 33;
    float zr = (O2f[k*72 + wf] + O2f[(64+k)*72 + 33+wf]) * 0.0078125f;
    float zi = (O2f[k*72 + 33+wf] - O2f[(64+k)*72 + wf]) * 0.0078125f;
    g_Zr[zo + idx] = zr;
    g_Zi[zo + idx] = zi;
  }
}

// ---------------------------------------------------------------------------
// K3 (tf32 mma): complex MLP via real-stacked GEMMs.  (unchanged)
// ---------------------------------------------------------------------------
__device__ __forceinline__ float gelu_f(float v) {
  return 0.5f*v*(1.0f + erff(v*0.70710678118654752f));
}
__device__ __forceinline__ float sshrink_f(float v) {
  float a = fabsf(v) - 0.01f;
  return a > 0.0f ? copysignf(a, v) : 0.0f;
}

__global__ __launch_bounds__(256) void k3_mma(
    const float* __restrict__ w1r, const float* __restrict__ w1i,
    const float* __restrict__ b1r, const float* __restrict__ b1i,
    const float* __restrict__ w2r, const float* __restrict__ w2i,
    const float* __restrict__ b2r, const float* __restrict__ b2i) {
  extern __shared__ float sm3f[];
  uint32_t* Asu = (uint32_t*)sm3f;          // [128 k][72 p]
  float*    Asf = sm3f;
  uint32_t* Bsu = (uint32_t*)sm3f + 9216;   // [32 k][136 n]
  float*    bs  = sm3f + 13568;
  int tid = threadIdx.x;
  int lane = tid & 31, wid = tid >> 5;
  int qr = lane >> 2, qc = lane & 3;
  int wm = (wid & 3) * 16;
  int wn = (wid >> 2) * 64;
  int bx = blockIdx.x;
  int nb = bx / 132, pt = bx % 132;
  size_t nbase = (size_t)nb*BSZ*NPTS + (size_t)pt*64;

  for (int idx = tid; idx < 4096; idx += 256) {
    int i = idx >> 6, p = idx & 63;
    Asu[i*72 + p]      = f2tf32(g_Zr[nbase + (size_t)i*NPTS + p]);
    Asu[(64+i)*72 + p] = f2tf32(g_Zi[nbase + (size_t)i*NPTS + p]);
  }
  if (tid < 64) {
    bs[tid]     = b1r[nb*64+tid]; bs[64+tid]  = b1i[nb*64+tid];
    bs[128+tid] = b2r[nb*64+tid]; bs[192+tid] = b2i[nb*64+tid];
  }

  float acc[8][4];

  #pragma unroll
  for (int layer = 0; layer < 2; ++layer) {
    const float* wr_ = layer ? w2r : w1r;
    const float* wi_ = layer ? w2i : w1i;
    #pragma unroll
    for (int nt=0;nt<8;++nt) {
      #pragma unroll
      for (int r=0;r<4;++r) acc[nt][r]=0.f;
    }
    for (int c0 = 0; c0 < 128; c0 += 32) {
      __syncthreads();
      #pragma unroll
      for (int it = 0; it < 4; ++it) {
        int slot = it*256 + tid;
        int kl = slot >> 5, c4 = slot & 31;
        int k = c0 + kl;
        float4 v; float sg = 1.f;
        if (k < 64) {
          if (c4 < 16) v = *(const float4*)&wr_[(size_t)nb*4096 + k*64 + c4*4];
          else         v = *(const float4*)&wi_[(size_t)nb*4096 + k*64 + (c4-16)*4];
        } else {
          int i = k - 64;
          if (c4 < 16) { v = *(const float4*)&wi_[(size_t)nb*4096 + i*64 + c4*4]; sg = -1.f; }
          else         v = *(const float4*)&wr_[(size_t)nb*4096 + i*64 + (c4-16)*4];
        }
        uint32_t* dst = &Bsu[kl*136 + c4*4];
        dst[0]=f2tf32(sg*v.x); dst[1]=f2tf32(sg*v.y);
        dst[2]=f2tf32(sg*v.z); dst[3]=f2tf32(sg*v.w);
      }
      __syncthreads();
      #pragma unroll
      for (int ks = 0; ks < 32; ks += 8) {
        uint32_t a[4];
        a[0] = Asu[(c0+ks+qc  )*72 + wm+qr  ];
        a[1] = Asu[(c0+ks+qc  )*72 + wm+qr+8];
        a[2] = Asu[(c0+ks+qc+4)*72 + wm+qr  ];
        a[3] = Asu[(c0+ks+qc+4)*72 + wm+qr+8];
        #pragma unroll
        for (int nt=0;nt<8;++nt) {
          uint32_t bfr[2];
          bfr[0] = Bsu[(ks+qc  )*136 + wn+nt*8+qr];
          bfr[1] = Bsu[(ks+qc+4)*136 + wn+nt*8+qr];
          mma1688(acc[nt], a, bfr);
        }
      }
    }
    __syncthreads();
    if (layer == 0) {
      #pragma unroll
      for (int nt=0;nt<8;++nt) {
        int j = wn + nt*8 + qc*2;
        Asu[(j  )*72 + wm+qr  ] = f2tf32(gelu_f(acc[nt][0] + bs[j  ]));
        Asu[(j+1)*72 + wm+qr  ] = f2tf32(gelu_f(acc[nt][1] + bs[j+1]));
        Asu[(j  )*72 + wm+qr+8] = f2tf32(gelu_f(acc[nt][2] + bs[j  ]));
        Asu[(j+1)*72 + wm+qr+8] = f2tf32(gelu_f(acc[nt][3] + bs[j+1]));
      }
    } else {
      #pragma unroll
      for (int nt=0;nt<8;++nt) {
        int j = wn + nt*8 + qc*2;
        Asf[(j  )*72 + wm+qr  ] = sshrink_f(acc[nt][0] + bs[128+j  ]);
        Asf[(j+1)*72 + wm+qr  ] = sshrink_f(acc[nt][1] + bs[128+j+1]);
        Asf[(j  )*72 + wm+qr+8] = sshrink_f(acc[nt][2] + bs[128+j  ]);
        Asf[(j+1)*72 + wm+qr+8] = sshrink_f(acc[nt][3] + bs[128+j+1]);
      }
    }
  }
  __syncthreads();
  for (int idx = tid; idx < 8192; idx += 256) {
    int j = idx >> 6, p = idx & 63;
    float y = Asf[j*72 + p];
    if (j < 64) {
      size_t o = nbase + (size_t)j*NPTS + p;
      g_Dr[o] = y - g_Zr[o];
    } else {
      size_t o = nbase + (size_t)(j-64)*NPTS + p;
      g_Di[o] = y - g_Zi[o];
    }
  }
}

// ---------------------------------------------------------------------------
// K45: fused inverse, cp.async double-buffered T3/T4 staging.
// smem uint32: R[9728] A0[4608] A1[4608] St0[1088] St1[1088] = 84480 B
// ---------------------------------------------------------------------------
#define K45_R  0
#define K45_A0 9728
#define K45_A1 14336
#define K45_S0 18944
#define K45_S1 20032
#define K45_SMEM 84480

__global__ __launch_bounds__(256) void k45_inv(const float* __restrict__ x) {
  extern __shared__ uint32_t smw[];
  uint32_t smb = smaddr(smw);
  uint32_t* R = smw + K45_R;

  int tid = threadIdx.x;
  int lane = tid & 31, wid = tid >> 5;
  int qr = lane >> 2, qc = lane & 3;
  int m0 = wid * 16;
  int bc = blockIdx.x;
  int b = bc >> 9, c = bc & 511;
  int n = c >> 6, i = c & 63;

  // prefetch first T3 chunk while gathering D
  auto load3 = [&](int ch) {
    int kc = ch * 32;
    uint32_t ab = smb + ((ch & 1) ? K45_A1 : K45_A0)*4u;
    #pragma unroll
    for (int it = 0; it < 4; ++it) {
      int s = it*256 + tid;
      int h = s >> 3, k4 = s & 7;
      cpa16(ab + (uint32_t)(h*36 + k4*4)*4u, &T3g[h*128 + kc + k4*4]);
    }
    cpa_commit();
  };
  load3(0);

  size_t dofs = ((size_t)n*BSZ + i)*NPTS + (size_t)b*2112;
  for (int idx = tid; idx < 2112; idx += 256) {
    int k = idx / 33, wf = idx % 33;
    float dr = g_Dr[dofs + idx], di = g_Di[dofs + idx];
    R[(k   )*72 + wf   ] = f2tf32(dr);
    R[(64+k)*72 + wf   ] = f2tf32(-di);
    R[(k   )*72 + 33+wf] = f2tf32(di);
    R[(64+k)*72 + 33+wf] = f2tf32(dr);
  }
  for (int idx = tid; idx < 128*6; idx += 256) {
    R[(idx/6)*72 + 66 + (idx % 6)] = 0u;
  }

  // ---- GEMM3: G = T3 @ B3, pipelined ----
  float acc3[9][4];
  #pragma unroll
  for (int nt=0;nt<9;++nt) {
    #pragma unroll
    for (int r=0;r<4;++r) acc3[nt][r]=0.f;
  }
  for (int ch = 0; ch < 4; ++ch) {
    if (ch < 3) { load3(ch + 1); cpa_wait1(); } else { cpa_wait0(); }
    __syncthreads();
    const uint32_t* At = smw + ((ch & 1) ? K45_A1 : K45_A0);
    #pragma unroll
    for (int ks = 0; ks < 4; ++ks) {
      int k8 = ks*8;
      int kc = ch * 32;
      uint32_t a[4];
      a[0] = At[(m0+qr  )*36 + k8+qc  ];
      a[1] = At[(m0+qr+8)*36 + k8+qc  ];
      a[2] = At[(m0+qr  )*36 + k8+qc+4];
      a[3] = At[(m0+qr+8)*36 + k8+qc+4];
      #pragma unroll
      for (int nt=0;nt<9;++nt) {
        uint32_t bfr[2];
        bfr[0] = R[(kc+k8+qc  )*72 + nt*8+qr];
        bfr[1] = R[(kc+k8+qc+4)*72 + nt*8+qr];
        mma1688(acc3[nt], a, bfr);
      }
    }
    __syncthreads();
  }
  // prefetch first T4 block before overwriting R with G
  auto load4 = [&](int ks) {
    uint32_t sb = smb + ((ks & 1) ? K45_S1 : K45_S0)*4u;
    #pragma unroll
    for (int it = 0; it < 2; ++it) {
      int s = it*256 + tid;
      if (s < 272) cpa16(sb + (uint32_t)s*16u, &T4g[ks*8*136 + s*4]);
    }
    cpa_commit();
  };
  load4(0);

  #pragma unroll
  for (int nt=0;nt<9;++nt) {
    int col = nt*8 + qc*2;
    R[(m0+qr  )*76 + col  ] = f2tf32(acc3[nt][0]);
    R[(m0+qr  )*76 + col+1] = f2tf32(acc3[nt][1]);
    R[(m0+qr+8)*76 + col  ] = f2tf32(acc3[nt][2]);
    R[(m0+qr+8)*76 + col+1] = f2tf32(acc3[nt][3]);
  }

  // ---- GEMM4: S' = G @ T4, pipelined over 9 blocks ----
  float acc4[16][4];
  #pragma unroll
  for (int nt=0;nt<16;++nt) {
    #pragma unroll
    for (int r=0;r<4;++r) acc4[nt][r]=0.f;
  }
  #pragma unroll
  for (int ks = 0; ks < 9; ++ks) {
    int k8 = ks*8;
    if (ks < 8) { load4(ks + 1); cpa_wait1(); } else { cpa_wait0(); }
    __syncthreads();
    const uint32_t* St = smw + ((ks & 1) ? K45_S1 : K45_S0);
    uint32_t a[4];
    a[0] = R[(m0+qr  )*76 + k8+qc  ];
    a[1] = R[(m0+qr+8)*76 + k8+qc  ];
    a[2] = R[(m0+qr  )*76 + k8+qc+4];
    a[3] = R[(m0+qr+8)*76 + k8+qc+4];
    #pragma unroll
    for (int nt=0;nt<16;++nt) {
      uint32_t bfr[2];
      bfr[0] = St[(qc  )*136 + nt*8+qr];
      bfr[1] = St[(qc+4)*136 + nt*8+qr];
      mma1688(acc4[nt], a, bfr);
    }
    __syncthreads();
  }

  const float* xp = x + (size_t)bc*16384;
  float* Sp = g_S + (size_t)bc*16384;
  #pragma unroll
  for (int nt=0;nt<16;++nt) {
    int col = nt*8 + qc*2;
    int r0 = m0 + qr, r1 = m0 + qr + 8;
    float2 x0 = *(const float2*)&xp[r0*128 + col];
    float2 x1 = *(const float2*)&xp[r1*128 + col];
    float2 s0, s1;
    s0.x = x0.x + acc4[nt][0]; s0.y = x0.y + acc4[nt][1];
    s1.x = x1.x + acc4[nt][2]; s1.y = x1.y + acc4[nt][3];
    *(float2*)&Sp[r0*128 + col] = s0;
    *(float2*)&Sp[r1*128 + col] = s1;
  }
}

// ---------------------------------------------------------------------------
// K6: 256-o-row tiles, 512 threads, cp.async 2-stage (unchanged)
// ---------------------------------------------------------------------------
#define K6_A0 0
#define K6_A1 9216
#define K6_B0 18432
#define K6_B1 22784
#define K6_SMEM 108544

__global__ __launch_bounds__(512) void k6_fuse_mma(const float* __restrict__ x,
                                                   const float* __restrict__ fw,
                                                   float* __restrict__ out) {
  extern __shared__ float sm6[];
  uint32_t smb = smaddr(sm6);
  int tid = threadIdx.x;
  int lane = tid & 31, wid = tid >> 5;
  int bx = blockIdx.x;
  int hwT = (bx & 127) * 128;
  int t2 = bx >> 7;
  int oT = (t2 & 1) * 256;
  int b  = t2 >> 1;
  const float* Sb = g_S + (size_t)b*CC*16384;

  int wm = (wid & 7) * 32;
  int wn = (wid >> 3) * 64;
  int qr = lane >> 2;
  int qc = lane & 3;

  float acc[2][8][4];
  #pragma unroll
  for (int mt=0;mt<2;++mt) {
    #pragma unroll
    for (int nt=0;nt<8;++nt) {
      #pragma unroll
      for (int r=0;r<4;++r) acc[mt][nt][r]=0.f;
    }
  }

  auto load_chunk = [&](int ch) {
    int c0 = ch * 32;
    int aoff = (ch & 1) ? K6_A1 : K6_A0;
    int boff = (ch & 1) ? K6_B1 : K6_B0;
    #pragma unroll
    for (int it = 0; it < 4; ++it) {
      int slot = it*512 + tid;
      int o = slot >> 3, k4 = slot & 7;
      cpa16(smb + (uint32_t)(aoff + o*36 + k4*4)*4u,
            &fw[(size_t)(oT+o)*512 + c0 + k4*4]);
    }
    #pragma unroll
    for (int it = 0; it < 2; ++it) {
      int slot = it*512 + tid;
      int k = slot >> 5, h4 = slot & 31;
      cpa16(smb + (uint32_t)(boff + k*136 + h4*4)*4u,
            &Sb[(size_t)(c0+k)*16384 + hwT + h4*4]);
    }
    cpa_commit();
  };

  load_chunk(0);
  for (int ch = 0; ch < 16; ++ch) {
    if (ch < 15) { load_chunk(ch + 1); cpa_wait1(); } else { cpa_wait0(); }
    __syncthreads();
    const float* Af = sm6 + ((ch & 1) ? K6_A1 : K6_A0);
    const float* Bf = sm6 + ((ch & 1) ? K6_B1 : K6_B0);
    #pragma unroll
    for (int ks = 0; ks < 32; ks += 8) {
      uint32_t afr[2][4];
      #pragma unroll
      for (int mt=0;mt<2;++mt) {
        int rb = wm + mt*16;
        afr[mt][0] = f2tf32(Af[(rb + qr     )*36 + ks + qc    ]);
        afr[mt][1] = f2tf32(Af[(rb + qr + 8 )*36 + ks + qc    ]);
        afr[mt][2] = f2tf32(Af[(rb + qr     )*36 + ks + qc + 4]);
        afr[mt][3] = f2tf32(Af[(rb + qr + 8 )*36 + ks + qc + 4]);
      }
      #pragma unroll
      for (int nt=0;nt<8;++nt) {
        int cb = wn + nt*8;
        uint32_t bfr[2];
        bfr[0] = f2tf32(Bf[(ks + qc    )*136 + cb + qr]);
        bfr[1] = f2tf32(Bf[(ks + qc + 4)*136 + cb + qr]);
        mma1688(acc[0][nt], afr[0], bfr);
        mma1688(acc[1][nt], afr[1], bfr);
      }
    }
    __syncthreads();
  }

  #pragma unroll
  for (int mt=0;mt<2;++mt) {
    int row0 = oT + wm + mt*16 + qr;
    #pragma unroll
    for (int nt=0;nt<8;++nt) {
      int col = hwT + wn + nt*8 + qc*2;
      size_t ob0 = ((size_t)(b*512 + row0    ))*16384 + col;
      size_t ob1 = ((size_t)(b*512 + row0 + 8))*16384 + col;
      float2 x0 = *(const float2*)&x[ob0];
      float2 x1 = *(const float2*)&x[ob1];
      float2 r0, r1;
      r0.x = x0.x + acc[mt][nt][0]; r0.y = x0.y + acc[mt][nt][1];
      r1.x = x1.x + acc[mt][nt][2]; r1.y = x1.y + acc[mt][nt][3];
      *(float2*)&out[ob0] = r0;
      *(float2*)&out[ob1] = r1;
    }
  }
}

// ---------------------------------------------------------------------------
extern "C" void kernel_launch(void* const* d_in, const int* in_sizes, int n_in,
                              void* d_out, int out_size) {
  const float* x   = (const float*)d_in[0];
  const float* w1r = (const float*)d_in[1];
  const float* w1i = (const float*)d_in[2];
  const float* b1r = (const float*)d_in[3];
  const float* b1i = (const float*)d_in[4];
  const float* w2r = (const float*)d_in[5];
  const float* w2i = (const float*)d_in[6];
  const float* b2r = (const float*)d_in[7];
  const float* b2i = (const float*)d_in[8];
  const float* fw  = (const float*)d_in[9];
  float* out = (float*)d_out;

  cudaFuncSetAttribute(k12_fwd, cudaFuncAttributeMaxDynamicSharedMemorySize, K12_SMEM);
  cudaFuncSetAttribute(k45_inv, cudaFuncAttributeMaxDynamicSharedMemorySize, K45_SMEM);
  cudaFuncSetAttribute(k3_mma,  cudaFuncAttributeMaxDynamicSharedMemorySize, 55296);
  cudaFuncSetAttribute(k6_fuse_mma, cudaFuncAttributeMaxDynamicSharedMemorySize, K6_SMEM);

  k0_twiddle<<<32, 256>>>();
  k12_fwd<<<BB*CC, 256, K12_SMEM>>>(x);
  k3_mma<<<NBK*132, 256, 55296>>>(w1r, w1i, b1r, b1i, w2r, w2i, b2r, b2i);
  k45_inv<<<BB*CC, 256, K45_SMEM>>>(x);
  k6_fuse_mma<<<BB*2*128, 512, K6_SMEM>>>(x, fw, out);
}

// round 17
// speedup vs baseline: 1.3493x; 1.0073x over previous
#include <cuda_runtime.h>
#include <math.h>
#include <stdint.h>

#define BB   4
#define CC   512
#define NBK  8
#define BSZ  64
#define WFM  33
#define KHM  64
#define NPTS (BB*KHM*WFM)     // 8448

// Z/D layout: [n][i][p]  (p = b*2112 + k*33 + wf)
__device__ float  g_Zr[NBK*BSZ*NPTS];
__device__ float  g_Zi[NBK*BSZ*NPTS];
__device__ float  g_Dr[NBK*BSZ*NPTS];
__device__ float  g_Di[NBK*BSZ*NPTS];
__device__ float  g_S[BB*CC*128*128];

__device__ uint32_t T1g[128*72];
__device__ uint32_t T2g[128*128];
__device__ uint32_t T3g[128*128];
__device__ uint32_t T4g[72*136];

__device__ __forceinline__ uint32_t f2tf32(float f) {
  uint32_t r; asm("cvt.rna.tf32.f32 %0, %1;" : "=r"(r) : "f"(f)); return r;
}
__device__ __forceinline__ void mma1688(float* d, const uint32_t* a, const uint32_t* b2) {
  asm volatile(
    "mma.sync.aligned.m16n8k8.row.col.f32.tf32.tf32.f32 "
    "{%0,%1,%2,%3}, {%4,%5,%6,%7}, {%8,%9}, {%0,%1,%2,%3};"
    : "+f"(d[0]), "+f"(d[1]), "+f"(d[2]), "+f"(d[3])
    : "r"(a[0]), "r"(a[1]), "r"(a[2]), "r"(a[3]), "r"(b2[0]), "r"(b2[1]));
}
__device__ __forceinline__ void cpa16(uint32_t dst, const void* src) {
  asm volatile("cp.async.ca.shared.global [%0], [%1], 16;" :: "r"(dst), "l"(src));
}
__device__ __forceinline__ void cpa_commit() {
  asm volatile("cp.async.commit_group;" ::: "memory");
}
__device__ __forceinline__ void cpa_wait0() {
  asm volatile("cp.async.wait_group 0;" ::: "memory");
}
__device__ __forceinline__ uint32_t smaddr(const void* p) {
  uint32_t a;
  asm("{ .reg .u64 t; cvta.to.shared.u64 t, %1; cvt.u32.u64 %0, t; }" : "=r"(a) : "l"(p));
  return a;
}

// ---------------------------------------------------------------------------
__global__ __launch_bounds__(256) void k0_twiddle() {
  int tid = blockIdx.x*256 + threadIdx.x;
  for (int idx = tid; idx < 128*72; idx += 256*32) {
    int w = idx / 72, nf = idx % 72;
    float v = 0.f;
    if (nf < 33)      v =  cospif((float)((w*nf) & 127) * (1.0f/64.0f));
    else if (nf < 66) v = -sinpif((float)((w*(nf-33)) & 127) * (1.0f/64.0f));
    T1g[idx] = f2tf32(v);
  }
  for (int idx = tid; idx < 128*128; idx += 256*32) {
    int m = idx >> 7, h = idx & 127;
    float v = (m < 64) ? cospif((float)((h*m) & 127) * (1.0f/64.0f))
                       : sinpif((float)((h*(m-64)) & 127) * (1.0f/64.0f));
    T2g[idx] = f2tf32(v);
  }
  for (int idx = tid; idx < 128*128; idx += 256*32) {
    int h = idx >> 7, kk = idx & 127;
    float v = (kk < 64) ? cospif((float)((h*kk) & 127) * (1.0f/64.0f))
                        : sinpif((float)((h*(kk-64)) & 127) * (1.0f/64.0f));
    T3g[idx] = f2tf32(v);
  }
  for (int idx = tid; idx < 72*136; idx += 256*32) {
    int kk = idx / 136, w = idx % 136;
    float v = 0.f;
    if (w < 128) {
      if (kk == 0)       v = 1.0f/128.0f;
      else if (kk < 33)  v =  (1.0f/64.0f) * cospif((float)((w*kk) & 127) * (1.0f/64.0f));
      else if (kk == 33) v = 0.f;
      else if (kk < 66)  v = -(1.0f/64.0f) * sinpif((float)((w*(kk-33)) & 127) * (1.0f/64.0f));
    }
    T4g[idx] = f2tf32(v);
  }
}

// ---------------------------------------------------------------------------
// K12: fused forward, one-sync-per-chunk cp.async pipeline.
// smem uint32: A0[4608] A1[4608] St0[2304] St1[2304] B2[9216] = 92160 B
// ---------------------------------------------------------------------------
#define K12_A0 0
#define K12_A1 4608
#define K12_S0 9216
#define K12_S1 11520
#define K12_B2 13824
#define K12_SMEM 92160

__global__ __launch_bounds__(256) void k12_fwd(const float* __restrict__ x) {
  extern __shared__ uint32_t smw[];
  uint32_t smb = smaddr(smw);
  uint32_t* B2 = smw + K12_B2;
  float* O2f = (float*)B2;

  int tid = threadIdx.x;
  int lane = tid & 31, wid = tid >> 5;
  int qr = lane >> 2, qc = lane & 3;
  int m0 = wid * 16;
  int bc = blockIdx.x;
  int b = bc >> 9, c = bc & 511;
  const float* xp = x + (size_t)bc * 16384;

  float acc[9][4];
  #pragma unroll
  for (int nt=0;nt<9;++nt) {
    #pragma unroll
    for (int r=0;r<4;++r) acc[nt][r]=0.f;
  }

  auto load1 = [&](int ch) {
    int kc = ch * 32;
    uint32_t ab = smb + ((ch & 1) ? K12_A1 : K12_A0)*4u;
    uint32_t sb = smb + ((ch & 1) ? K12_S1 : K12_S0)*4u;
    #pragma unroll
    for (int it = 0; it < 4; ++it) {
      int s = it*256 + tid;
      int h = s >> 3, k4 = s & 7;
      cpa16(ab + (uint32_t)(h*36 + k4*4)*4u, &xp[h*128 + kc + k4*4]);
    }
    #pragma unroll
    for (int it = 0; it < 3; ++it) {
      int s = it*256 + tid;
      if (s < 576) cpa16(sb + (uint32_t)s*16u, &T1g[kc*72 + s*4]);
    }
    cpa_commit();
  };

  load1(0);
  for (int ch = 0; ch < 4; ++ch) {
    cpa_wait0();
    __syncthreads();
    if (ch < 3) load1(ch + 1);
    const float* Af = (const float*)(smw + ((ch & 1) ? K12_A1 : K12_A0));
    const uint32_t* St = smw + ((ch & 1) ? K12_S1 : K12_S0);
    #pragma unroll
    for (int ks = 0; ks < 4; ++ks) {
      int k8 = ks*8;
      uint32_t a[4];
      a[0] = f2tf32(Af[(m0+qr  )*36 + k8+qc  ]);
      a[1] = f2tf32(Af[(m0+qr+8)*36 + k8+qc  ]);
      a[2] = f2tf32(Af[(m0+qr  )*36 + k8+qc+4]);
      a[3] = f2tf32(Af[(m0+qr+8)*36 + k8+qc+4]);
      #pragma unroll
      for (int nt=0;nt<9;++nt) {
        uint32_t bfr[2];
        bfr[0] = St[(k8+qc  )*72 + nt*8+qr];
        bfr[1] = St[(k8+qc+4)*72 + nt*8+qr];
        mma1688(acc[nt], a, bfr);
      }
    }
  }
  __syncthreads();      // all GEMM1 reads done; A buffers reusable

  auto load2 = [&](int ch) {
    int kc = ch * 32;
    uint32_t ab = smb + ((ch & 1) ? K12_A1 : K12_A0)*4u;
    #pragma unroll
    for (int it = 0; it < 4; ++it) {
      int s = it*256 + tid;
      int m = s >> 3, k4 = s & 7;
      cpa16(ab + (uint32_t)(m*36 + k4*4)*4u, &T2g[m*128 + kc + k4*4]);
    }
    cpa_commit();
  };
  load2(0);
  #pragma unroll
  for (int nt=0;nt<9;++nt) {
    int col = nt*8 + qc*2;
    B2[(m0+qr  )*72 + col  ] = f2tf32(acc[nt][0]);
    B2[(m0+qr  )*72 + col+1] = f2tf32(acc[nt][1]);
    B2[(m0+qr+8)*72 + col  ] = f2tf32(acc[nt][2]);
    B2[(m0+qr+8)*72 + col+1] = f2tf32(acc[nt][3]);
  }

  #pragma unroll
  for (int nt=0;nt<9;++nt) {
    #pragma unroll
    for (int r=0;r<4;++r) acc[nt][r]=0.f;
  }
  for (int ch = 0; ch < 4; ++ch) {
    cpa_wait0();
    __syncthreads();    // first iter also publishes B2
    if (ch < 3) load2(ch + 1);
    int kc = ch * 32;
    const uint32_t* At = smw + ((ch & 1) ? K12_A1 : K12_A0);
    #pragma unroll
    for (int ks = 0; ks < 4; ++ks) {
      int k8 = ks*8;
      uint32_t a[4];
      a[0] = At[(m0+qr  )*36 + k8+qc  ];
      a[1] = At[(m0+qr+8)*36 + k8+qc  ];
      a[2] = At[(m0+qr  )*36 + k8+qc+4];
      a[3] = At[(m0+qr+8)*36 + k8+qc+4];
      #pragma unroll
      for (int nt=0;nt<9;++nt) {
        uint32_t bfr[2];
        bfr[0] = B2[(kc+k8+qc  )*72 + nt*8+qr];
        bfr[1] = B2[(kc+k8+qc+4)*72 + nt*8+qr];
        mma1688(acc[nt], a, bfr);
      }
    }
  }
  __syncthreads();      // B2 reads done; safe to overwrite with O2
  #pragma unroll
  for (int nt=0;nt<9;++nt) {
    int col = nt*8 + qc*2;
    O2f[(m0+qr  )*72 + col  ] = acc[nt][0];
    O2f[(m0+qr  )*72 + col+1] = acc[nt][1];
    O2f[(m0+qr+8)*72 + col  ] = acc[nt][2];
    O2f[(m0+qr+8)*72 + col+1] = acc[nt][3];
  }
  __syncthreads();

  int n = c >> 6, i2 = c & 63;
  size_t zo = ((size_t)n*BSZ + i2)*NPTS + (size_t)b*2112;
  for (int idx = tid; idx < 2112; idx += 256) {
    int k = idx / 33, wf = idx % 33;
    float zr = (O2f[k*72 + wf] + O2f[(64+k)*72 + 33+wf]) * 0.0078125f;
    float zi = (O2f[k*72 + 33+wf] - O2f[(64+k)*72 + wf]) * 0.0078125f;
    g_Zr[zo + idx] = zr;
    g_Zi[zo + idx] = zi;
  }
}

// ---------------------------------------------------------------------------
// K3 (tf32 mma): complex MLP via real-stacked GEMMs.  (unchanged)
// ---------------------------------------------------------------------------
__device__ __forceinline__ float gelu_f(float v) {
  return 0.5f*v*(1.0f + erff(v*0.70710678118654752f));
}
__device__ __forceinline__ float sshrink_f(float v) {
  float a = fabsf(v) - 0.01f;
  return a > 0.0f ? copysignf(a, v) : 0.0f;
}

__global__ __launch_bounds__(256) void k3_mma(
    const float* __restrict__ w1r, const float* __restrict__ w1i,
    const float* __restrict__ b1r, const float* __restrict__ b1i,
    const float* __restrict__ w2r, const float* __restrict__ w2i,
    const float* __restrict__ b2r, const float* __restrict__ b2i) {
  extern __shared__ float sm3f[];
  uint32_t* Asu = (uint32_t*)sm3f;          // [128 k][72 p]
  float*    Asf = sm3f;
  uint32_t* Bsu = (uint32_t*)sm3f + 9216;   // [32 k][136 n]
  float*    bs  = sm3f + 13568;
  int tid = threadIdx.x;
  int lane = tid & 31, wid = tid >> 5;
  int qr = lane >> 2, qc = lane & 3;
  int wm = (wid & 3) * 16;
  int wn = (wid >> 2) * 64;
  int bx = blockIdx.x;
  int nb = bx / 132, pt = bx % 132;
  size_t nbase = (size_t)nb*BSZ*NPTS + (size_t)pt*64;

  for (int idx = tid; idx < 4096; idx += 256) {
    int i = idx >> 6, p = idx & 63;
    Asu[i*72 + p]      = f2tf32(g_Zr[nbase + (size_t)i*NPTS + p]);
    Asu[(64+i)*72 + p] = f2tf32(g_Zi[nbase + (size_t)i*NPTS + p]);
  }
  if (tid < 64) {
    bs[tid]     = b1r[nb*64+tid]; bs[64+tid]  = b1i[nb*64+tid];
    bs[128+tid] = b2r[nb*64+tid]; bs[192+tid] = b2i[nb*64+tid];
  }

  float acc[8][4];

  #pragma unroll
  for (int layer = 0; layer < 2; ++layer) {
    const float* wr_ = layer ? w2r : w1r;
    const float* wi_ = layer ? w2i : w1i;
    #pragma unroll
    for (int nt=0;nt<8;++nt) {
      #pragma unroll
      for (int r=0;r<4;++r) acc[nt][r]=0.f;
    }
    for (int c0 = 0; c0 < 128; c0 += 32) {
      __syncthreads();
      #pragma unroll
      for (int it = 0; it < 4; ++it) {
        int slot = it*256 + tid;
        int kl = slot >> 5, c4 = slot & 31;
        int k = c0 + kl;
        float4 v; float sg = 1.f;
        if (k < 64) {
          if (c4 < 16) v = *(const float4*)&wr_[(size_t)nb*4096 + k*64 + c4*4];
          else         v = *(const float4*)&wi_[(size_t)nb*4096 + k*64 + (c4-16)*4];
        } else {
          int i = k - 64;
          if (c4 < 16) { v = *(const float4*)&wi_[(size_t)nb*4096 + i*64 + c4*4]; sg = -1.f; }
          else         v = *(const float4*)&wr_[(size_t)nb*4096 + i*64 + (c4-16)*4];
        }
        uint32_t* dst = &Bsu[kl*136 + c4*4];
        dst[0]=f2tf32(sg*v.x); dst[1]=f2tf32(sg*v.y);
        dst[2]=f2tf32(sg*v.z); dst[3]=f2tf32(sg*v.w);
      }
      __syncthreads();
      #pragma unroll
      for (int ks = 0; ks < 32; ks += 8) {
        uint32_t a[4];
        a[0] = Asu[(c0+ks+qc  )*72 + wm+qr  ];
        a[1] = Asu[(c0+ks+qc  )*72 + wm+qr+8];
        a[2] = Asu[(c0+ks+qc+4)*72 + wm+qr  ];
        a[3] = Asu[(c0+ks+qc+4)*72 + wm+qr+8];
        #pragma unroll
        for (int nt=0;nt<8;++nt) {
          uint32_t bfr[2];
          bfr[0] = Bsu[(ks+qc  )*136 + wn+nt*8+qr];
          bfr[1] = Bsu[(ks+qc+4)*136 + wn+nt*8+qr];
          mma1688(acc[nt], a, bfr);
        }
      }
    }
    __syncthreads();
    if (layer == 0) {
      #pragma unroll
      for (int nt=0;nt<8;++nt) {
        int j = wn + nt*8 + qc*2;
        Asu[(j  )*72 + wm+qr  ] = f2tf32(gelu_f(acc[nt][0] + bs[j  ]));
        Asu[(j+1)*72 + wm+qr  ] = f2tf32(gelu_f(acc[nt][1] + bs[j+1]));
        Asu[(j  )*72 + wm+qr+8] = f2tf32(gelu_f(acc[nt][2] + bs[j  ]));
        Asu[(j+1)*72 + wm+qr+8] = f2tf32(gelu_f(acc[nt][3] + bs[j+1]));
      }
    } else {
      #pragma unroll
      for (int nt=0;nt<8;++nt) {
        int j = wn + nt*8 + qc*2;
        Asf[(j  )*72 + wm+qr  ] = sshrink_f(acc[nt][0] + bs[128+j  ]);
        Asf[(j+1)*72 + wm+qr  ] = sshrink_f(acc[nt][1] + bs[128+j+1]);
        Asf[(j  )*72 + wm+qr+8] = sshrink_f(acc[nt][2] + bs[128+j  ]);
        Asf[(j+1)*72 + wm+qr+8] = sshrink_f(acc[nt][3] + bs[128+j+1]);
      }
    }
  }
  __syncthreads();
  for (int idx = tid; idx < 8192; idx += 256) {
    int j = idx >> 6, p = idx & 63;
    float y = Asf[j*72 + p];
    if (j < 64) {
      size_t o = nbase + (size_t)j*NPTS + p;
      g_Dr[o] = y - g_Zr[o];
    } else {
      size_t o = nbase + (size_t)(j-64)*NPTS + p;
      g_Di[o] = y - g_Zi[o];
    }
  }
}

// ---------------------------------------------------------------------------
// K45: fused inverse, one-sync-per-chunk; GEMM4 staged 24 T4-rows/chunk.
// smem uint32: R[9728] A0[4608] A1[4608] S0[3264] S1[3264] = 101888 B
// ---------------------------------------------------------------------------
#define K45_R  0
#define K45_A0 9728
#define K45_A1 14336
#define K45_S0 18944
#define K45_S1 22208
#define K45_SMEM 101888

__global__ __launch_bounds__(256) void k45_inv(const float* __restrict__ x) {
  extern __shared__ uint32_t smw[];
  uint32_t smb = smaddr(smw);
  uint32_t* R = smw + K45_R;

  int tid = threadIdx.x;
  int lane = tid & 31, wid = tid >> 5;
  int qr = lane >> 2, qc = lane & 3;
  int m0 = wid * 16;
  int bc = blockIdx.x;
  int b = bc >> 9, c = bc & 511;
  int n = c >> 6, i = c & 63;

  auto load3 = [&](int ch) {
    int kc = ch * 32;
    uint32_t ab = smb + ((ch & 1) ? K45_A1 : K45_A0)*4u;
    #pragma unroll
    for (int it = 0; it < 4; ++it) {
      int s = it*256 + tid;
      int h = s >> 3, k4 = s & 7;
      cpa16(ab + (uint32_t)(h*36 + k4*4)*4u, &T3g[h*128 + kc + k4*4]);
    }
    cpa_commit();
  };
  load3(0);

  size_t dofs = ((size_t)n*BSZ + i)*NPTS + (size_t)b*2112;
  for (int idx = tid; idx < 2112; idx += 256) {
    int k = idx / 33, wf = idx % 33;
    float dr = g_Dr[dofs + idx], di = g_Di[dofs + idx];
    R[(k   )*72 + wf   ] = f2tf32(dr);
    R[(64+k)*72 + wf   ] = f2tf32(-di);
    R[(k   )*72 + 33+wf] = f2tf32(di);
    R[(64+k)*72 + 33+wf] = f2tf32(dr);
  }
  for (int idx = tid; idx < 128*6; idx += 256) {
    R[(idx/6)*72 + 66 + (idx % 6)] = 0u;
  }

  // ---- GEMM3: G = T3 @ B3, one sync per chunk ----
  float acc3[9][4];
  #pragma unroll
  for (int nt=0;nt<9;++nt) {
    #pragma unroll
    for (int r=0;r<4;++r) acc3[nt][r]=0.f;
  }
  for (int ch = 0; ch < 4; ++ch) {
    cpa_wait0();
    __syncthreads();            // first iter also publishes R gather
    if (ch < 3) load3(ch + 1);
    const uint32_t* At = smw + ((ch & 1) ? K45_A1 : K45_A0);
    int kc = ch * 32;
    #pragma unroll
    for (int ks = 0; ks < 4; ++ks) {
      int k8 = ks*8;
      uint32_t a[4];
      a[0] = At[(m0+qr  )*36 + k8+qc  ];
      a[1] = At[(m0+qr+8)*36 + k8+qc  ];
      a[2] = At[(m0+qr  )*36 + k8+qc+4];
      a[3] = At[(m0+qr+8)*36 + k8+qc+4];
      #pragma unroll
      for (int nt=0;nt<9;++nt) {
        uint32_t bfr[2];
        bfr[0] = R[(kc+k8+qc  )*72 + nt*8+qr];
        bfr[1] = R[(kc+k8+qc+4)*72 + nt*8+qr];
        mma1688(acc3[nt], a, bfr);
      }
    }
  }
  __syncthreads();              // all B3 reads done; R reusable for G

  auto load4 = [&](int it) {
    uint32_t sb = smb + ((it & 1) ? K45_S1 : K45_S0)*4u;
    #pragma unroll
    for (int q = 0; q < 4; ++q) {
      int s = q*256 + tid;
      if (s < 816) cpa16(sb + (uint32_t)s*16u, &T4g[it*24*136 + s*4]);
    }
    cpa_commit();
  };
  load4(0);

  #pragma unroll
  for (int nt=0;nt<9;++nt) {
    int col = nt*8 + qc*2;
    R[(m0+qr  )*76 + col  ] = f2tf32(acc3[nt][0]);
    R[(m0+qr  )*76 + col+1] = f2tf32(acc3[nt][1]);
    R[(m0+qr+8)*76 + col  ] = f2tf32(acc3[nt][2]);
    R[(m0+qr+8)*76 + col+1] = f2tf32(acc3[nt][3]);
  }

  // ---- GEMM4: S' = G @ T4, 3 chunks of 24 rows, one sync each ----
  float acc4[16][4];
  #pragma unroll
  for (int nt=0;nt<16;++nt) {
    #pragma unroll
    for (int r=0;r<4;++r) acc4[nt][r]=0.f;
  }
  #pragma unroll
  for (int it = 0; it < 3; ++it) {
    cpa_wait0();
    __syncthreads();            // first iter also publishes G
    if (it < 2) load4(it + 1);
    const uint32_t* St = smw + ((it & 1) ? K45_S1 : K45_S0);
    #pragma unroll
    for (int kb = 0; kb < 3; ++kb) {
      int k8 = it*24 + kb*8;
      uint32_t a[4];
      a[0] = R[(m0+qr  )*76 + k8+qc  ];
      a[1] = R[(m0+qr+8)*76 + k8+qc  ];
      a[2] = R[(m0+qr  )*76 + k8+qc+4];
      a[3] = R[(m0+qr+8)*76 + k8+qc+4];
      #pragma unroll
      for (int nt=0;nt<16;++nt) {
        uint32_t bfr[2];
        bfr[0] = St[(kb*8+qc  )*136 + nt*8+qr];
        bfr[1] = St[(kb*8+qc+4)*136 + nt*8+qr];
        mma1688(acc4[nt], a, bfr);
      }
    }
  }

  const float* xp = x + (size_t)bc*16384;
  float* Sp = g_S + (size_t)bc*16384;
  #pragma unroll
  for (int nt=0;nt<16;++nt) {
    int col = nt*8 + qc*2;
    int r0 = m0 + qr, r1 = m0 + qr + 8;
    float2 x0 = *(const float2*)&xp[r0*128 + col];
    float2 x1 = *(const float2*)&xp[r1*128 + col];
    float2 s0, s1;
    s0.x = x0.x + acc4[nt][0]; s0.y = x0.y + acc4[nt][1];
    s1.x = x1.x + acc4[nt][2]; s1.y = x1.y + acc4[nt][3];
    *(float2*)&Sp[r0*128 + col] = s0;
    *(float2*)&Sp[r1*128 + col] = s1;
  }
}

// ---------------------------------------------------------------------------
// K6: 256-o-row tiles, 512 threads, one sync per chunk.
// ---------------------------------------------------------------------------
#define K6_A0 0
#define K6_A1 9216
#define K6_B0 18432
#define K6_B1 22784
#define K6_SMEM 108544

__global__ __launch_bounds__(512) void k6_fuse_mma(const float* __restrict__ x,
                                                   const float* __restrict__ fw,
                                                   float* __restrict__ out) {
  extern __shared__ float sm6[];
  uint32_t smb = smaddr(sm6);
  int tid = threadIdx.x;
  int lane = tid & 31, wid = tid >> 5;
  int bx = blockIdx.x;
  int hwT = (bx & 127) * 128;
  int t2 = bx >> 7;
  int oT = (t2 & 1) * 256;
  int b  = t2 >> 1;
  const float* Sb = g_S + (size_t)b*CC*16384;

  int wm = (wid & 7) * 32;
  int wn = (wid >> 3) * 64;
  int qr = lane >> 2;
  int qc = lane & 3;

  float acc[2][8][4];
  #pragma unroll
  for (int mt=0;mt<2;++mt) {
    #pragma unroll
    for (int nt=0;nt<8;++nt) {
      #pragma unroll
      for (int r=0;r<4;++r) acc[mt][nt][r]=0.f;
    }
  }

  auto load_chunk = [&](int ch) {
    int c0 = ch * 32;
    int aoff = (ch & 1) ? K6_A1 : K6_A0;
    int boff = (ch & 1) ? K6_B1 : K6_B0;
    #pragma unroll
    for (int it = 0; it < 4; ++it) {
      int slot = it*512 + tid;
      int o = slot >> 3, k4 = slot & 7;
      cpa16(smb + (uint32_t)(aoff + o*36 + k4*4)*4u,
            &fw[(size_t)(oT+o)*512 + c0 + k4*4]);
    }
    #pragma unroll
    for (int it = 0; it < 2; ++it) {
      int slot = it*512 + tid;
      int k = slot >> 5, h4 = slot & 31;
      cpa16(smb + (uint32_t)(boff + k*136 + h4*4)*4u,
            &Sb[(size_t)(c0+k)*16384 + hwT + h4*4]);
    }
    cpa_commit();
  };

  load_chunk(0);
  for (int ch = 0; ch < 16; ++ch) {
    cpa_wait0();
    __syncthreads();
    if (ch < 15) load_chunk(ch + 1);
    const float* Af = sm6 + ((ch & 1) ? K6_A1 : K6_A0);
    const float* Bf = sm6 + ((ch & 1) ? K6_B1 : K6_B0);
    #pragma unroll
    for (int ks = 0; ks < 32; ks += 8) {
      uint32_t afr[2][4];
      #pragma unroll
      for (int mt=0;mt<2;++mt) {
        int rb = wm + mt*16;
        afr[mt][0] = f2tf32(Af[(rb + qr     )*36 + ks + qc    ]);
        afr[mt][1] = f2tf32(Af[(rb + qr + 8 )*36 + ks + qc    ]);
        afr[mt][2] = f2tf32(Af[(rb + qr     )*36 + ks + qc + 4]);
        afr[mt][3] = f2tf32(Af[(rb + qr + 8 )*36 + ks + qc + 4]);
      }
      #pragma unroll
      for (int nt=0;nt<8;++nt) {
        int cb = wn + nt*8;
        uint32_t bfr[2];
        bfr[0] = f2tf32(Bf[(ks + qc    )*136 + cb + qr]);
        bfr[1] = f2tf32(Bf[(ks + qc + 4)*136 + cb + qr]);
        mma1688(acc[0][nt], afr[0], bfr);
        mma1688(acc[1][nt], afr[1], bfr);
      }
    }
  }

  #pragma unroll
  for (int mt=0;mt<2;++mt) {
    int row0 = oT + wm + mt*16 + qr;
    #pragma unroll
    for (int nt=0;nt<8;++nt) {
      int col = hwT + wn + nt*8 + qc*2;
      size_t ob0 = ((size_t)(b*512 + row0    ))*16384 + col;
      size_t ob1 = ((size_t)(b*512 + row0 + 8))*16384 + col;
      float2 x0 = *(const float2*)&x[ob0];
      float2 x1 = *(const float2*)&x[ob1];
      float2 r0, r1;
      r0.x = x0.x + acc[mt][nt][0]; r0.y = x0.y + acc[mt][nt][1];
      r1.x = x1.x + acc[mt][nt][2]; r1.y = x1.y + acc[mt][nt][3];
      *(float2*)&out[ob0] = r0;
      *(float2*)&out[ob1] = r1;
    }
  }
}

// ---------------------------------------------------------------------------
extern "C" void kernel_launch(void* const* d_in, const int* in_sizes, int n_in,
                              void* d_out, int out_size) {
  const float* x   = (const float*)d_in[0];
  const float* w1r = (const float*)d_in[1];
  const float* w1i = (const float*)d_in[2];
  const float* b1r = (const float*)d_in[3];
  const float* b1i = (const float*)d_in[4];
  const float* w2r = (const float*)d_in[5];
  const float* w2i = (const float*)d_in[6];
  const float* b2r = (const float*)d_in[7];
  const float* b2i = (const float*)d_in[8];
  const float* fw  = (const float*)d_in[9];
  float* out = (float*)d_out;

  cudaFuncSetAttribute(k12_fwd, cudaFuncAttributeMaxDynamicSharedMemorySize, K12_SMEM);
  cudaFuncSetAttribute(k45_inv, cudaFuncAttributeMaxDynamicSharedMemorySize, K45_SMEM);
  cudaFuncSetAttribute(k3_mma,  cudaFuncAttributeMaxDynamicSharedMemorySize, 55296);
  cudaFuncSetAttribute(k6_fuse_mma, cudaFuncAttributeMaxDynamicSharedMemorySize, K6_SMEM);

  k0_twiddle<<<32, 256>>>();
  k12_fwd<<<BB*CC, 256, K12_SMEM>>>(x);
  k3_mma<<<NBK*132, 256, 55296>>>(w1r, w1i, b1r, b1i, w2r, w2i, b2r, b2i);
  k45_inv<<<BB*CC, 256, K45_SMEM>>>(x);
  k6_fuse_mma<<<BB*2*128, 512, K6_SMEM>>>(x, fw, out);
}